// round 11
// baseline (speedup 1.0000x reference)
#include <cuda_runtime.h>
#include <cstdint>
#include <math.h>

// ---------------------------------------------------------------------------
// Problem constants
// ---------------------------------------------------------------------------
namespace {
constexpr int B_   = 8;
constexpr int S_   = 512;
constexpr int D_   = 1024;
constexpr int H_   = 8;
constexpr int DP_  = 128;              // head dim
constexpr int BH_  = B_ * H_;          // 64
constexpr int MS_  = B_ * S_;          // 4096  (rows of x)
constexpr int NR_  = 96 * S_;          // 49152 RNN rows
constexpr int ROWS_ = BH_ * S_;        // 32768 (b,h,q) rows
constexpr int NOUT_ = MS_ * D_;        // 4194304 elements of `out`
constexpr float INV_SCALE = 0.08838834764831845f;  // 1/sqrt(128)
// smem: A[3][128][20] + B_tn[3][128][20]  /  B_nn[3][16][136]
constexpr int SMEM_TN = (3 * 128 * 20 + 3 * 128 * 20) * 4;   // 61440
constexpr int SMEM_NN = (3 * 128 * 20 + 3 * 16 * 136) * 4;   // 56832
}

// ---------------------------------------------------------------------------
// Scratch (static device globals -- no runtime allocation allowed)
// ---------------------------------------------------------------------------
__device__ float g_q  [BH_ * S_ * DP_];
__device__ float g_k  [BH_ * S_ * DP_];
__device__ float g_v  [BH_ * S_ * DP_];
__device__ float g_ctx[BH_ * S_ * DP_];
__device__ float g_A  [NR_ * DP_];
__device__ float g_Bm [NR_ * DP_];
__device__ float g_H1f[NR_ * DP_];
__device__ float g_H1b[NR_ * DP_];
__device__ float g_Yf [NR_ * DP_];
__device__ float g_P  [ROWS_ * 65];
__device__ float g_R  [ROWS_ * 65];
__device__ int   g_mask[MS_];
__device__ float g_attn_fb[(size_t)BH_ * S_ * S_];
// tf32-rounded operand copies
__device__ float g_xr  [MS_ * D_];
__device__ float g_Wqr [D_ * D_];
__device__ float g_Wkr [D_ * D_];
__device__ float g_Wvr [D_ * D_];
__device__ float g_Wor [D_ * D_];
__device__ float g_Wihfr[DP_ * DP_];
__device__ float g_Whhfr[DP_ * DP_];
__device__ float g_Wihbr[DP_ * DP_];
__device__ float g_Whhbr[DP_ * DP_];

// ---------------------------------------------------------------------------
// tf32 / cp.async helpers
// ---------------------------------------------------------------------------
__device__ __forceinline__ unsigned f2tf(float x) {
    unsigned r;
    asm("cvt.rna.tf32.f32 %0, %1;" : "=r"(r) : "f"(x));
    return r;
}
__device__ __forceinline__ float rtf(float x) { return __uint_as_float(f2tf(x)); }

__device__ __forceinline__ void mma_tf32(float* d, const unsigned* a, const unsigned* b) {
    asm volatile(
        "mma.sync.aligned.m16n8k8.row.col.f32.tf32.tf32.f32 "
        "{%0,%1,%2,%3}, {%4,%5,%6,%7}, {%8,%9}, {%0,%1,%2,%3};\n"
        : "+f"(d[0]), "+f"(d[1]), "+f"(d[2]), "+f"(d[3])
        : "r"(a[0]), "r"(a[1]), "r"(a[2]), "r"(a[3]), "r"(b[0]), "r"(b[1]));
}

__device__ __forceinline__ void cp16(void* s, const void* g) {
    unsigned a = (unsigned)__cvta_generic_to_shared(s);
    asm volatile("cp.async.cg.shared.global [%0], [%1], 16;" :: "r"(a), "l"(g));
}
__device__ __forceinline__ void cp_commit() { asm volatile("cp.async.commit_group;"); }
__device__ __forceinline__ void cp_wait1()  { asm volatile("cp.async.wait_group 1;"); }

// ---------------------------------------------------------------------------
// 128x128 tf32 MMA cores, 128 threads = 4 warps (2M x 2N), warp tile 64x64.
// 3-stage cp.async pipeline; operands must already be tf32-rounded in gmem.
//   mm4_tn: C = A * B^T  (rowA(r,k)/rowB(r,k) -> const float* [row r, col k])
//   mm4_nn: C = A * B    (rowB(k,n) -> const float* [row k, col n])
// Per warp per k8: 16 A-LDS + 16 B-LDS for 32 MMAs.
// ---------------------------------------------------------------------------
template <class FA, class FB, class FC>
__device__ __forceinline__ void mm4_tn(int K, FA rowA, FB rowB, FC storeC) {
    extern __shared__ unsigned sm_[];
    unsigned (*As)[128][20] = reinterpret_cast<unsigned(*)[128][20]>(sm_);
    unsigned (*Bs)[128][20] = reinterpret_cast<unsigned(*)[128][20]>(sm_ + 3 * 128 * 20);
    const int tid  = threadIdx.x;
    const int lane = tid & 31, warp = tid >> 5;
    const int la3  = lane & 3, lg = lane >> 2;
    const int wm   = (warp & 1) * 64, wn = (warp >> 1) * 64;
    float acc[4][8][4] = {};
    const int nk = K / 16;
    auto issue = [&](int st, int k0) {
#pragma unroll
        for (int c = 0; c < 4; c++) {
            cp16(&As[st][tid][c * 4], rowA(tid, k0 + c * 4));
            cp16(&Bs[st][tid][c * 4], rowB(tid, k0 + c * 4));
        }
    };
    issue(0, 0);  cp_commit();
    issue(1, 16); cp_commit();
    int st = 0;
    for (int it = 0; it < nk; it++) {
        cp_wait1();
        __syncthreads();
        if (it + 2 < nk) {
            int ns = st + 2; if (ns >= 3) ns -= 3;
            issue(ns, (it + 2) * 16);
        }
        cp_commit();
#pragma unroll
        for (int kc = 0; kc < 16; kc += 8) {
            unsigned af[4][4], bf[8][2];
#pragma unroll
            for (int mi = 0; mi < 4; mi++) {
                int m0 = wm + 16 * mi;
                af[mi][0] = As[st][m0 + lg][kc + la3];
                af[mi][1] = As[st][m0 + 8 + lg][kc + la3];
                af[mi][2] = As[st][m0 + lg][kc + 4 + la3];
                af[mi][3] = As[st][m0 + 8 + lg][kc + 4 + la3];
            }
#pragma unroll
            for (int nj = 0; nj < 8; nj++) {
                int n0 = wn + 8 * nj;
                bf[nj][0] = Bs[st][n0 + lg][kc + la3];
                bf[nj][1] = Bs[st][n0 + lg][kc + 4 + la3];
            }
#pragma unroll
            for (int mi = 0; mi < 4; mi++)
#pragma unroll
                for (int nj = 0; nj < 8; nj++) mma_tf32(acc[mi][nj], af[mi], bf[nj]);
        }
        if (++st == 3) st = 0;
    }
#pragma unroll
    for (int mi = 0; mi < 4; mi++)
#pragma unroll
        for (int nj = 0; nj < 8; nj++) {
            int r = wm + 16 * mi + lg, c = wn + 8 * nj + 2 * la3;
            storeC(r,     c,     acc[mi][nj][0]);
            storeC(r,     c + 1, acc[mi][nj][1]);
            storeC(r + 8, c,     acc[mi][nj][2]);
            storeC(r + 8, c + 1, acc[mi][nj][3]);
        }
}

template <class FA, class FB, class FC>
__device__ __forceinline__ void mm4_nn(int K, FA rowA, FB rowB, FC storeC) {
    extern __shared__ unsigned sm_[];
    unsigned (*As)[128][20] = reinterpret_cast<unsigned(*)[128][20]>(sm_);
    unsigned (*Bs)[16][136] = reinterpret_cast<unsigned(*)[16][136]>(sm_ + 3 * 128 * 20);
    const int tid  = threadIdx.x;
    const int lane = tid & 31, warp = tid >> 5;
    const int la3  = lane & 3, lg = lane >> 2;
    const int wm   = (warp & 1) * 64, wn = (warp >> 1) * 64;
    float acc[4][8][4] = {};
    const int nk = K / 16;
    auto issue = [&](int st, int k0) {
#pragma unroll
        for (int c = 0; c < 4; c++)
            cp16(&As[st][tid][c * 4], rowA(tid, k0 + c * 4));
#pragma unroll
        for (int j = 0; j < 4; j++) {
            int idx = tid + 128 * j;           // 0..511 chunk
            int row = idx >> 5, c16 = idx & 31;
            cp16(&Bs[st][row][c16 * 4], rowB(k0 + row, c16 * 4));
        }
    };
    issue(0, 0);  cp_commit();
    issue(1, 16); cp_commit();
    int st = 0;
    for (int it = 0; it < nk; it++) {
        cp_wait1();
        __syncthreads();
        if (it + 2 < nk) {
            int ns = st + 2; if (ns >= 3) ns -= 3;
            issue(ns, (it + 2) * 16);
        }
        cp_commit();
#pragma unroll
        for (int kc = 0; kc < 16; kc += 8) {
            unsigned af[4][4], bf[8][2];
#pragma unroll
            for (int mi = 0; mi < 4; mi++) {
                int m0 = wm + 16 * mi;
                af[mi][0] = As[st][m0 + lg][kc + la3];
                af[mi][1] = As[st][m0 + 8 + lg][kc + la3];
                af[mi][2] = As[st][m0 + lg][kc + 4 + la3];
                af[mi][3] = As[st][m0 + 8 + lg][kc + 4 + la3];
            }
#pragma unroll
            for (int nj = 0; nj < 8; nj++) {
                int n0 = wn + 8 * nj;
                bf[nj][0] = Bs[st][kc + la3][n0 + lg];
                bf[nj][1] = Bs[st][kc + 4 + la3][n0 + lg];
            }
#pragma unroll
            for (int mi = 0; mi < 4; mi++)
#pragma unroll
                for (int nj = 0; nj < 8; nj++) mma_tf32(acc[mi][nj], af[mi], bf[nj]);
        }
        if (++st == 3) st = 0;
    }
#pragma unroll
    for (int mi = 0; mi < 4; mi++)
#pragma unroll
        for (int nj = 0; nj < 8; nj++) {
            int r = wm + 16 * mi + lg, c = wn + 8 * nj + 2 * la3;
            storeC(r,     c,     acc[mi][nj][0]);
            storeC(r,     c + 1, acc[mi][nj][1]);
            storeC(r + 8, c,     acc[mi][nj][2]);
            storeC(r + 8, c + 1, acc[mi][nj][3]);
        }
}

// ---------------------------------------------------------------------------
// tf32 pre-rounding of GEMM operands (rna, once)
// ---------------------------------------------------------------------------
__global__ void round_kernel(const float4* __restrict__ src, float4* __restrict__ dst, int n4) {
    int i = blockIdx.x * blockDim.x + threadIdx.x;
    if (i >= n4) return;
    float4 v = src[i];
    v.x = rtf(v.x); v.y = rtf(v.y); v.z = rtf(v.z); v.w = rtf(v.w);
    dst[i] = v;
}

// ---------------------------------------------------------------------------
// 0) Mask normalization (detect uint8 / int32 / float32 encodings)
// ---------------------------------------------------------------------------
__global__ void mask_norm_kernel(const void* raw) {
    __shared__ int f_int, f_flt;
    const unsigned int* w = (const unsigned int*)raw;
    int t = threadIdx.x;  // 1024 threads
    if (t == 0) { f_int = 1; f_flt = 1; }
    __syncthreads();
    unsigned int x = w[t];
    if (x != 0u && x != 1u) f_int = 0;
    if (x != 0u && x != 0x3F800000u) f_flt = 0;
    __syncthreads();
    if (f_int) {
        for (int i = t; i < MS_; i += 1024) g_mask[i] = (int)w[i];
    } else if (f_flt) {
        const float* f = (const float*)raw;
        for (int i = t; i < MS_; i += 1024) g_mask[i] = (f[i] != 0.f);
    } else {
        const unsigned char* bts = (const unsigned char*)raw;
        for (int i = t; i < MS_; i += 1024) g_mask[i] = (bts[i] != 0);
    }
}

// ---------------------------------------------------------------------------
// 1) QKV projections + bias + mask-zero + head-major scatter (rounded out)
// ---------------------------------------------------------------------------
__global__ void __launch_bounds__(128) qkv_kernel(
    const float* __restrict__ bq, const float* __restrict__ bk,
    const float* __restrict__ bv) {
    const int z = blockIdx.z;
    const float* W    = (z == 0) ? g_Wqr : (z == 1) ? g_Wkr : g_Wvr;
    const float* bias = (z == 0) ? bq : (z == 1) ? bk : bv;
    float* out        = (z == 0) ? g_q : (z == 1) ? g_k : g_v;
    const int bm = blockIdx.y * 128, bn = blockIdx.x * 128;
    mm4_tn(D_,
        [&](int r, int k) { return g_xr + (size_t)(bm + r) * D_ + k; },
        [&](int r, int k) { return W + (size_t)(bn + r) * D_ + k; },
        [&](int il, int jl, float v) {
            int m = bm + il, n = bn + jl;
            int b = m >> 9, s = m & 511;
            int h = n >> 7, d = n & 127;
            float val = g_mask[m] ? 0.f : rtf(v + bias[n]);
            out[((size_t)((b * H_ + h) * S_ + s)) * DP_ + d] = val;
        });
}

// ---------------------------------------------------------------------------
// 2) RNN input GEMMs
// ---------------------------------------------------------------------------
__device__ __forceinline__ const float* feats_row(int rr) {
    int f = rr >> 14;
    int rem = rr & 16383;
    int bh4 = rem >> 9;
    int s   = rem & 511;
    int b = bh4 >> 2, hh = bh4 & 3;
    const float* src = (f == 0) ? g_q : (f == 1) ? g_k : g_v;
    return src + ((size_t)((b * H_ + 4 + hh) * S_ + s)) * DP_;
}

__global__ void __launch_bounds__(128) rnn_in_kernel(
    const float* __restrict__ bih_f, const float* __restrict__ bih_b) {
    const int z = blockIdx.z;
    const float* W    = z ? g_Wihbr : g_Wihfr;
    const float* bias = z ? bih_b : bih_f;
    float* dst        = z ? g_Bm : g_A;
    const int bm = blockIdx.y * 128;
    mm4_tn(DP_,
        [&](int r, int k) { return feats_row(bm + r) + k; },
        [&](int r, int k) { return W + (size_t)r * DP_ + k; },
        [&](int il, int jl, float v) {
            dst[(size_t)(bm + il) * DP_ + jl] = v + bias[jl];
        });
}

// ---------------------------------------------------------------------------
// 3) First RNN step (elementwise; rounded out -- H1 feeds GEMMs)
// ---------------------------------------------------------------------------
__global__ void rnn_h1_kernel(const float* __restrict__ bih_f,
                              const float* __restrict__ bhh_f,
                              const float* __restrict__ bhh_b) {
    int gid = blockIdx.x * blockDim.x + threadIdx.x;
    if (gid >= NR_ * DP_) return;
    int r = gid >> 7, d = gid & 127;
    int s = r & 511;
    float af = s ? g_A[gid - DP_] : bih_f[d];
    g_H1f[gid] = rtf(tanhf(af + bhh_f[d]));
    g_H1b[gid] = rtf(tanhf(g_Bm[gid] + bhh_b[d]));
}

// ---------------------------------------------------------------------------
// 4) Forward step 2:  Yf = tanh( A + H1f@Whh_f^T + bhh_f )
// ---------------------------------------------------------------------------
__global__ void __launch_bounds__(128) rnn_h2f_kernel(const float* __restrict__ bhh_f) {
    const int bm = blockIdx.y * 128;
    mm4_tn(DP_,
        [&](int r, int k) { return g_H1f + (size_t)(bm + r) * DP_ + k; },
        [&](int r, int k) { return g_Whhfr + (size_t)r * DP_ + k; },
        [&](int il, int jl, float v) {
            size_t idx = (size_t)(bm + il) * DP_ + jl;
            g_Yf[idx] = tanhf(v + g_A[idx] + bhh_f[jl]);
        });
}

// ---------------------------------------------------------------------------
// 5) Backward step 2 + combine + scatter back into q/k/v heads 4..7 (rounded)
// ---------------------------------------------------------------------------
__global__ void __launch_bounds__(128) rnn_h2b_kernel(
    const float* __restrict__ bih_b, const float* __restrict__ bhh_b) {
    const int bm = blockIdx.y * 128;
    mm4_tn(DP_,
        [&](int r, int k) { return g_H1b + (size_t)(bm + r) * DP_ + k; },
        [&](int r, int k) { return g_Whhbr + (size_t)r * DP_ + k; },
        [&](int il, int jl, float v) {
            int m = bm + il, n = jl;
            int s = m & 511;
            float shiftB = s ? g_Bm[(size_t)(m - 1) * DP_ + n] : bih_b[n];
            float y = g_Yf[(size_t)m * DP_ + n] + tanhf(v + shiftB + bhh_b[n]);
            int f = m >> 14, rem = m & 16383, bh4 = rem >> 9;
            int b = bh4 >> 2, hh = bh4 & 3;
            float* dst = (f == 0) ? g_q : (f == 1) ? g_k : g_v;
            dst[((size_t)((b * H_ + 4 + hh) * S_ + s)) * DP_ + n] = rtf(y);
        });
}

// ---------------------------------------------------------------------------
// 6) P[row,j] = (q[row] . rel_emb[j]) / SCALE
// ---------------------------------------------------------------------------
__global__ void p_kernel(const float* __restrict__ rel_emb) {
    int gid = blockIdx.x * blockDim.x + threadIdx.x;
    if (gid >= ROWS_ * 65) return;
    int row = gid / 65, j = gid - row * 65;
    const float* qr = g_q + (size_t)row * DP_;
    const float* er = rel_emb + (size_t)j * DP_;
    float s = 0.f;
#pragma unroll 8
    for (int d = 0; d < DP_; d++) s = fmaf(qr[d], er[d], s);
    g_P[gid] = s * INV_SCALE;
}

// ---------------------------------------------------------------------------
// 7) scores (pre-softmax) into the attn buffer
// ---------------------------------------------------------------------------
__global__ void __launch_bounds__(128) scores_kernel(float* __restrict__ attn,
                                                     int attn_in_out) {
    float* ap = attn_in_out ? attn : g_attn_fb;
    const int z = blockIdx.z;
    const int b = z >> 3;
    const int bm = blockIdx.y * 128, bn = blockIdx.x * 128;
    const float* qb = g_q + (size_t)z * S_ * DP_;
    const float* kb = g_k + (size_t)z * S_ * DP_;
    mm4_tn(DP_,
        [&](int r, int k) { return qb + (size_t)(bm + r) * DP_ + k; },
        [&](int r, int k) { return kb + (size_t)(bn + r) * DP_ + k; },
        [&](int il, int jl, float v) {
            int qi = bm + il, ki = bn + jl;
            float val;
            if (g_mask[b * S_ + ki]) {
                val = -1e18f;
            } else {
                int off = ki - qi;
                off = off < -32 ? -32 : (off > 32 ? 32 : off);
                val = v * INV_SCALE + g_P[((size_t)z * S_ + qi) * 65 + off + 32];
            }
            ap[(size_t)z * S_ * S_ + (size_t)qi * S_ + ki] = val;
        });
}

// ---------------------------------------------------------------------------
// 8) Softmax per row + bucketed rel sums R
// ---------------------------------------------------------------------------
__device__ __forceinline__ float blk_reduce(float v, float* red, bool is_max) {
#pragma unroll
    for (int o = 16; o > 0; o >>= 1) {
        float w = __shfl_xor_sync(0xffffffffu, v, o);
        v = is_max ? fmaxf(v, w) : (v + w);
    }
    int warp = threadIdx.x >> 5, lane = threadIdx.x & 31;
    if (lane == 0) red[warp] = v;
    __syncthreads();
    float r = red[0];
#pragma unroll
    for (int i = 1; i < 8; i++) r = is_max ? fmaxf(r, red[i]) : (r + red[i]);
    __syncthreads();
    return r;
}

__global__ void __launch_bounds__(256) softmax_kernel(float* __restrict__ attn,
                                                      int attn_in_out) {
    float* ap = attn_in_out ? attn : g_attn_fb;
    int row = blockIdx.x;
    int q = row & 511;
    float* p = ap + (size_t)row * S_;
    __shared__ float sh[S_];
    __shared__ float red[8];
    int t = threadIdx.x;
    float v0 = p[t], v1 = p[t + 256];
    float mx = blk_reduce(fmaxf(v0, v1), red, true);
    float e0 = expf(v0 - mx), e1 = expf(v1 - mx);
    float sum = blk_reduce(e0 + e1, red, false);
    float inv = 1.f / sum;
    e0 *= inv; e1 *= inv;
    p[t] = e0; p[t + 256] = e1;
    sh[t] = e0; sh[t + 256] = e1;
    float r0 = 0.f, r64 = 0.f;
    if (t <= q - 32)        r0  += e0;
    if (t >= q + 32)        r64 += e0;
    if (t + 256 <= q - 32)  r0  += e1;
    if (t + 256 >= q + 32)  r64 += e1;
    r0  = blk_reduce(r0,  red, false);
    r64 = blk_reduce(r64, red, false);
    float* Rr = g_R + (size_t)row * 65;
    if (t == 0) { Rr[0] = r0; Rr[64] = r64; }
    if (t >= 1 && t <= 63) {
        int k = q + t - 32;
        Rr[t] = (k >= 0 && k < S_) ? sh[k] : 0.f;
    }
}

// ---------------------------------------------------------------------------
// 9) ctx = attn @ v  (NN, per bh)
// ---------------------------------------------------------------------------
__global__ void __launch_bounds__(128) ctx_kernel(const float* __restrict__ attn,
                                                  int attn_in_out) {
    const float* ap = attn_in_out ? attn : g_attn_fb;
    const int z = blockIdx.z;
    const int bm = blockIdx.y * 128;
    const float* Ab = ap + (size_t)z * S_ * S_;
    const float* Vb = g_v + (size_t)z * S_ * DP_;
    mm4_nn(S_,
        [&](int r, int k) { return Ab + (size_t)(bm + r) * S_ + k; },
        [&](int k, int n) { return Vb + (size_t)k * DP_ + n; },
        [&](int il, int jl, float v) {
            g_ctx[(size_t)z * S_ * DP_ + (size_t)(bm + il) * DP_ + jl] = v;
        });
}

// ---------------------------------------------------------------------------
// 10) ctx += R @ rel_emb  (rounded out -- feeds out GEMM)
// ---------------------------------------------------------------------------
__global__ void ctx_rel_kernel(const float* __restrict__ rel_emb) {
    int gid = blockIdx.x * blockDim.x + threadIdx.x;
    if (gid >= ROWS_ * DP_) return;
    int row = gid >> 7, d = gid & 127;
    const float* Rr = g_R + (size_t)row * 65;
    float s = 0.f;
#pragma unroll
    for (int j = 0; j < 65; j++) s = fmaf(Rr[j], rel_emb[(size_t)j * DP_ + d], s);
    g_ctx[gid] = rtf(g_ctx[gid] + s);
}

// ---------------------------------------------------------------------------
// 11) out = ctx_perm @ Wo^T + bo
// ---------------------------------------------------------------------------
__global__ void __launch_bounds__(128) out_kernel(const float* __restrict__ bo,
                                                  float* __restrict__ out) {
    const int bm = blockIdx.y * 128, bn = blockIdx.x * 128;
    mm4_tn(D_,
        [&](int r, int k) {
            int m = bm + r;
            int b = m >> 9, s = m & 511;
            int h = k >> 7, d = k & 127;
            return g_ctx + ((size_t)((b * H_ + h) * S_ + s)) * DP_ + d;
        },
        [&](int r, int k) { return g_Wor + (size_t)(bn + r) * D_ + k; },
        [&](int il, int jl, float v) {
            int m = bm + il, n = bn + jl;
            out[(size_t)m * D_ + n] = v + bo[n];
        });
}

// ---------------------------------------------------------------------------
// Host launcher
// ---------------------------------------------------------------------------
extern "C" void kernel_launch(void* const* d_in, const int* in_sizes, int n_in,
                              void* d_out, int out_size) {
    const float* x     = (const float*)d_in[0];
    const void*  mask  = d_in[1];
    const float* Wq    = (const float*)d_in[2];
    const float* bq    = (const float*)d_in[3];
    const float* Wk    = (const float*)d_in[4];
    const float* bk    = (const float*)d_in[5];
    const float* Wv    = (const float*)d_in[6];
    const float* bv    = (const float*)d_in[7];
    const float* Wo    = (const float*)d_in[8];
    const float* bo    = (const float*)d_in[9];
    const float* rel   = (const float*)d_in[10];
    const float* Wih_f = (const float*)d_in[11];
    const float* Whh_f = (const float*)d_in[12];
    const float* bih_f = (const float*)d_in[13];
    const float* bhh_f = (const float*)d_in[14];
    const float* Wih_b = (const float*)d_in[15];
    const float* Whh_b = (const float*)d_in[16];
    const float* bih_b = (const float*)d_in[17];
    const float* bhh_b = (const float*)d_in[18];

    float* out = (float*)d_out;
    const int attn_in_out = (out_size >= NOUT_ + BH_ * S_ * S_) ? 1 : 0;
    float* attn = attn_in_out ? (out + NOUT_) : nullptr;

    static int smem_set = 0;
    if (!smem_set) {
        cudaFuncSetAttribute(qkv_kernel,     cudaFuncAttributeMaxDynamicSharedMemorySize, SMEM_TN);
        cudaFuncSetAttribute(rnn_in_kernel,  cudaFuncAttributeMaxDynamicSharedMemorySize, SMEM_TN);
        cudaFuncSetAttribute(rnn_h2f_kernel, cudaFuncAttributeMaxDynamicSharedMemorySize, SMEM_TN);
        cudaFuncSetAttribute(rnn_h2b_kernel, cudaFuncAttributeMaxDynamicSharedMemorySize, SMEM_TN);
        cudaFuncSetAttribute(scores_kernel,  cudaFuncAttributeMaxDynamicSharedMemorySize, SMEM_TN);
        cudaFuncSetAttribute(ctx_kernel,     cudaFuncAttributeMaxDynamicSharedMemorySize, SMEM_NN);
        cudaFuncSetAttribute(out_kernel,     cudaFuncAttributeMaxDynamicSharedMemorySize, SMEM_TN);
        smem_set = 1;
    }

    // tf32 pre-rounding (rna) of all GEMM operand tensors
    auto rnd = [&](const float* src, float* dst, int n) {
        round_kernel<<<(n / 4 + 255) / 256, 256>>>((const float4*)src, (float4*)dst, n / 4);
    };
    float* p_xr;  cudaGetSymbolAddress((void**)&p_xr,  g_xr);
    float* p_wq;  cudaGetSymbolAddress((void**)&p_wq,  g_Wqr);
    float* p_wk;  cudaGetSymbolAddress((void**)&p_wk,  g_Wkr);
    float* p_wv;  cudaGetSymbolAddress((void**)&p_wv,  g_Wvr);
    float* p_wo;  cudaGetSymbolAddress((void**)&p_wo,  g_Wor);
    float* p_wif; cudaGetSymbolAddress((void**)&p_wif, g_Wihfr);
    float* p_whf; cudaGetSymbolAddress((void**)&p_whf, g_Whhfr);
    float* p_wib; cudaGetSymbolAddress((void**)&p_wib, g_Wihbr);
    float* p_whb; cudaGetSymbolAddress((void**)&p_whb, g_Whhbr);
    rnd(x, p_xr, MS_ * D_);
    rnd(Wq, p_wq, D_ * D_);
    rnd(Wk, p_wk, D_ * D_);
    rnd(Wv, p_wv, D_ * D_);
    rnd(Wo, p_wo, D_ * D_);
    rnd(Wih_f, p_wif, DP_ * DP_);
    rnd(Whh_f, p_whf, DP_ * DP_);
    rnd(Wih_b, p_wib, DP_ * DP_);
    rnd(Whh_b, p_whb, DP_ * DP_);

    mask_norm_kernel<<<1, 1024>>>(mask);

    qkv_kernel<<<dim3(D_ / 128, MS_ / 128, 3), 128, SMEM_TN>>>(bq, bk, bv);

    rnn_in_kernel<<<dim3(1, NR_ / 128, 2), 128, SMEM_TN>>>(bih_f, bih_b);
    rnn_h1_kernel<<<(NR_ * DP_) / 256, 256>>>(bih_f, bhh_f, bhh_b);
    rnn_h2f_kernel<<<dim3(1, NR_ / 128), 128, SMEM_TN>>>(bhh_f);
    rnn_h2b_kernel<<<dim3(1, NR_ / 128), 128, SMEM_TN>>>(bih_b, bhh_b);

    p_kernel<<<(ROWS_ * 65 + 255) / 256, 256>>>(rel);

    scores_kernel<<<dim3(S_ / 128, S_ / 128, BH_), 128, SMEM_TN>>>(attn, attn_in_out);
    softmax_kernel<<<ROWS_, 256>>>(attn, attn_in_out);
    ctx_kernel<<<dim3(1, S_ / 128, BH_), 128, SMEM_NN>>>(attn, attn_in_out);
    ctx_rel_kernel<<<(ROWS_ * DP_) / 256, 256>>>(rel);
    out_kernel<<<dim3(D_ / 128, MS_ / 128), 128, SMEM_TN>>>(bo, out);
}

// round 12
// speedup vs baseline: 1.1422x; 1.1422x over previous
#include <cuda_runtime.h>
#include <cstdint>
#include <math.h>

// ---------------------------------------------------------------------------
// Problem constants
// ---------------------------------------------------------------------------
namespace {
constexpr int B_   = 8;
constexpr int S_   = 512;
constexpr int D_   = 1024;
constexpr int H_   = 8;
constexpr int DP_  = 128;              // head dim
constexpr int BH_  = B_ * H_;          // 64
constexpr int MS_  = B_ * S_;          // 4096  (rows of x)
constexpr int NR_  = 96 * S_;          // 49152 RNN rows
constexpr int ROWS_ = BH_ * S_;        // 32768 (b,h,q) rows
constexpr int NOUT_ = MS_ * D_;        // 4194304 elements of `out`
constexpr float INV_SCALE = 0.08838834764831845f;  // 1/sqrt(128)
// smem: A[3][128][20] + B_tn[3][128][20]  /  B_nn[3][16][136]
constexpr int SMEM_TN = (3 * 128 * 20 + 3 * 128 * 20) * 4;   // 61440
constexpr int SMEM_NN = (3 * 128 * 20 + 3 * 16 * 136) * 4;   // 56832
}

// ---------------------------------------------------------------------------
// Scratch (static device globals -- no runtime allocation allowed)
// ---------------------------------------------------------------------------
__device__ float g_q  [BH_ * S_ * DP_];
__device__ float g_k  [BH_ * S_ * DP_];
__device__ float g_v  [BH_ * S_ * DP_];
__device__ float g_ctx[BH_ * S_ * DP_];
__device__ float g_A  [NR_ * DP_];
__device__ float g_Bm [NR_ * DP_];
__device__ float g_H1f[NR_ * DP_];
__device__ float g_H1b[NR_ * DP_];
__device__ float g_Yf [NR_ * DP_];
__device__ float g_P  [ROWS_ * 65];
__device__ float g_R  [ROWS_ * 65];
__device__ int   g_mask[MS_];
__device__ int   g_rowidx[MS_];        // compacted unmasked row indices
__device__ int   g_nrows;              // number of unmasked rows
__device__ float g_attn_fb[(size_t)BH_ * S_ * S_];
// tf32-rounded operand copies
__device__ float g_xr  [MS_ * D_];
__device__ float g_Wqr [D_ * D_];
__device__ float g_Wkr [D_ * D_];
__device__ float g_Wvr [D_ * D_];
__device__ float g_Wor [D_ * D_];
__device__ float g_Wihfr[DP_ * DP_];
__device__ float g_Whhfr[DP_ * DP_];
__device__ float g_Wihbr[DP_ * DP_];
__device__ float g_Whhbr[DP_ * DP_];

// ---------------------------------------------------------------------------
// tf32 / cp.async helpers
// ---------------------------------------------------------------------------
__device__ __forceinline__ unsigned f2tf(float x) {
    unsigned r;
    asm("cvt.rna.tf32.f32 %0, %1;" : "=r"(r) : "f"(x));
    return r;
}
__device__ __forceinline__ float rtf(float x) { return __uint_as_float(f2tf(x)); }

__device__ __forceinline__ void mma_tf32(float* d, const unsigned* a, const unsigned* b) {
    asm volatile(
        "mma.sync.aligned.m16n8k8.row.col.f32.tf32.tf32.f32 "
        "{%0,%1,%2,%3}, {%4,%5,%6,%7}, {%8,%9}, {%0,%1,%2,%3};\n"
        : "+f"(d[0]), "+f"(d[1]), "+f"(d[2]), "+f"(d[3])
        : "r"(a[0]), "r"(a[1]), "r"(a[2]), "r"(a[3]), "r"(b[0]), "r"(b[1]));
}

__device__ __forceinline__ void cp16(void* s, const void* g) {
    unsigned a = (unsigned)__cvta_generic_to_shared(s);
    asm volatile("cp.async.cg.shared.global [%0], [%1], 16;" :: "r"(a), "l"(g));
}
__device__ __forceinline__ void cp_commit() { asm volatile("cp.async.commit_group;"); }
__device__ __forceinline__ void cp_wait1()  { asm volatile("cp.async.wait_group 1;"); }

// ---------------------------------------------------------------------------
// 128x128 tf32 MMA cores with cp.async 3-stage pipeline (R7 proven core).
// 256 threads = 8 warps (2M x 4N), warp tile 64x32.
// ---------------------------------------------------------------------------
template <class FA, class FB, class FC>
__device__ __forceinline__ void ca_tn(int K, FA rowA, FB rowB, FC storeC) {
    extern __shared__ unsigned sm_[];
    unsigned (*As)[128][20] = reinterpret_cast<unsigned(*)[128][20]>(sm_);
    unsigned (*Bs)[128][20] = reinterpret_cast<unsigned(*)[128][20]>(sm_ + 3 * 128 * 20);
    const int tid  = threadIdx.x;
    const int lane = tid & 31, warp = tid >> 5;
    const int la3  = lane & 3, lg = lane >> 2;
    const int wm   = (warp & 1) * 64, wn = (warp >> 1) * 32;
    const int lr   = tid >> 2, lc = (tid & 3) * 4;
    float acc[4][4][4] = {};
    const int nk = K / 16;
    auto issue = [&](int st, int k0) {
        cp16(&As[st][lr][lc],      rowA(lr,      k0 + lc));
        cp16(&As[st][lr + 64][lc], rowA(lr + 64, k0 + lc));
        cp16(&Bs[st][lr][lc],      rowB(lr,      k0 + lc));
        cp16(&Bs[st][lr + 64][lc], rowB(lr + 64, k0 + lc));
    };
    issue(0, 0);  cp_commit();
    issue(1, 16); cp_commit();
    int st = 0;
    for (int it = 0; it < nk; it++) {
        cp_wait1();
        __syncthreads();
        if (it + 2 < nk) {
            int ns = st + 2; if (ns >= 3) ns -= 3;
            issue(ns, (it + 2) * 16);
        }
        cp_commit();
#pragma unroll
        for (int kc = 0; kc < 16; kc += 8) {
            unsigned af[4][4], bf[4][2];
#pragma unroll
            for (int mi = 0; mi < 4; mi++) {
                int m0 = wm + 16 * mi;
                af[mi][0] = As[st][m0 + lg][kc + la3];
                af[mi][1] = As[st][m0 + 8 + lg][kc + la3];
                af[mi][2] = As[st][m0 + lg][kc + 4 + la3];
                af[mi][3] = As[st][m0 + 8 + lg][kc + 4 + la3];
            }
#pragma unroll
            for (int nj = 0; nj < 4; nj++) {
                int n0 = wn + 8 * nj;
                bf[nj][0] = Bs[st][n0 + lg][kc + la3];
                bf[nj][1] = Bs[st][n0 + lg][kc + 4 + la3];
            }
#pragma unroll
            for (int mi = 0; mi < 4; mi++)
#pragma unroll
                for (int nj = 0; nj < 4; nj++) mma_tf32(acc[mi][nj], af[mi], bf[nj]);
        }
        if (++st == 3) st = 0;
    }
#pragma unroll
    for (int mi = 0; mi < 4; mi++)
#pragma unroll
        for (int nj = 0; nj < 4; nj++) {
            int r = wm + 16 * mi + lg, c = wn + 8 * nj + 2 * la3;
            storeC(r,     c,     acc[mi][nj][0]);
            storeC(r,     c + 1, acc[mi][nj][1]);
            storeC(r + 8, c,     acc[mi][nj][2]);
            storeC(r + 8, c + 1, acc[mi][nj][3]);
        }
}

template <class FA, class FB, class FC>
__device__ __forceinline__ void ca_nn(int K, FA rowA, FB rowB, FC storeC) {
    extern __shared__ unsigned sm_[];
    unsigned (*As)[128][20] = reinterpret_cast<unsigned(*)[128][20]>(sm_);
    unsigned (*Bs)[16][136] = reinterpret_cast<unsigned(*)[16][136]>(sm_ + 3 * 128 * 20);
    const int tid  = threadIdx.x;
    const int lane = tid & 31, warp = tid >> 5;
    const int la3  = lane & 3, lg = lane >> 2;
    const int wm   = (warp & 1) * 64, wn = (warp >> 1) * 32;
    const int lr   = tid >> 2, lc = (tid & 3) * 4;
    const int br   = tid >> 5, bc = (tid & 31) * 4;
    float acc[4][4][4] = {};
    const int nk = K / 16;
    auto issue = [&](int st, int k0) {
        cp16(&As[st][lr][lc],      rowA(lr,      k0 + lc));
        cp16(&As[st][lr + 64][lc], rowA(lr + 64, k0 + lc));
        cp16(&Bs[st][br][bc],      rowB(k0 + br,     bc));
        cp16(&Bs[st][br + 8][bc],  rowB(k0 + br + 8, bc));
    };
    issue(0, 0);  cp_commit();
    issue(1, 16); cp_commit();
    int st = 0;
    for (int it = 0; it < nk; it++) {
        cp_wait1();
        __syncthreads();
        if (it + 2 < nk) {
            int ns = st + 2; if (ns >= 3) ns -= 3;
            issue(ns, (it + 2) * 16);
        }
        cp_commit();
#pragma unroll
        for (int kc = 0; kc < 16; kc += 8) {
            unsigned af[4][4], bf[4][2];
#pragma unroll
            for (int mi = 0; mi < 4; mi++) {
                int m0 = wm + 16 * mi;
                af[mi][0] = As[st][m0 + lg][kc + la3];
                af[mi][1] = As[st][m0 + 8 + lg][kc + la3];
                af[mi][2] = As[st][m0 + lg][kc + 4 + la3];
                af[mi][3] = As[st][m0 + 8 + lg][kc + 4 + la3];
            }
#pragma unroll
            for (int nj = 0; nj < 4; nj++) {
                int n0 = wn + 8 * nj;
                bf[nj][0] = Bs[st][kc + la3][n0 + lg];
                bf[nj][1] = Bs[st][kc + 4 + la3][n0 + lg];
            }
#pragma unroll
            for (int mi = 0; mi < 4; mi++)
#pragma unroll
                for (int nj = 0; nj < 4; nj++) mma_tf32(acc[mi][nj], af[mi], bf[nj]);
        }
        if (++st == 3) st = 0;
    }
#pragma unroll
    for (int mi = 0; mi < 4; mi++)
#pragma unroll
        for (int nj = 0; nj < 4; nj++) {
            int r = wm + 16 * mi + lg, c = wn + 8 * nj + 2 * la3;
            storeC(r,     c,     acc[mi][nj][0]);
            storeC(r,     c + 1, acc[mi][nj][1]);
            storeC(r + 8, c,     acc[mi][nj][2]);
            storeC(r + 8, c + 1, acc[mi][nj][3]);
        }
}

// ---------------------------------------------------------------------------
// tf32 pre-rounding of GEMM operands (rna, once)
// ---------------------------------------------------------------------------
__global__ void round_kernel(const float4* __restrict__ src, float4* __restrict__ dst, int n4) {
    int i = blockIdx.x * blockDim.x + threadIdx.x;
    if (i >= n4) return;
    float4 v = src[i];
    v.x = rtf(v.x); v.y = rtf(v.y); v.z = rtf(v.z); v.w = rtf(v.w);
    dst[i] = v;
}

// ---------------------------------------------------------------------------
// 0) Mask normalization + row compaction (single block)
// ---------------------------------------------------------------------------
__global__ void mask_norm_kernel(const void* raw) {
    __shared__ int f_int, f_flt;
    const unsigned int* w = (const unsigned int*)raw;
    int t = threadIdx.x;  // 1024 threads
    if (t == 0) { f_int = 1; f_flt = 1; g_nrows = 0; }
    __syncthreads();
    unsigned int x = w[t];
    if (x != 0u && x != 1u) f_int = 0;
    if (x != 0u && x != 0x3F800000u) f_flt = 0;
    __syncthreads();
    if (f_int) {
        for (int i = t; i < MS_; i += 1024) g_mask[i] = (int)w[i];
    } else if (f_flt) {
        const float* f = (const float*)raw;
        for (int i = t; i < MS_; i += 1024) g_mask[i] = (f[i] != 0.f);
    } else {
        const unsigned char* bts = (const unsigned char*)raw;
        for (int i = t; i < MS_; i += 1024) g_mask[i] = (bts[i] != 0);
    }
    __syncthreads();
    // compaction: list of unmasked row indices (order-free, scatter-back by idx)
    for (int i = t; i < MS_; i += 1024) {
        if (!g_mask[i]) {
            int pos = atomicAdd(&g_nrows, 1);
            g_rowidx[pos] = i;
        }
    }
}

// ---------------------------------------------------------------------------
// 0b) Zero-fill q/k/v for masked rows (their GEMM result is skipped)
// ---------------------------------------------------------------------------
__global__ void zero_masked_kernel() {
    int i = blockIdx.x * 256 + threadIdx.x;
    if (i >= MS_ * D_) return;
    int m = i >> 10;
    if (!g_mask[m]) return;
    int n = i & 1023;
    int b = m >> 9, s = m & 511;
    int h = n >> 7, d = n & 127;
    size_t off = ((size_t)((b * H_ + h) * S_ + s)) * DP_ + d;
    g_q[off] = 0.f; g_k[off] = 0.f; g_v[off] = 0.f;
}

// ---------------------------------------------------------------------------
// 1) QKV projections on COMPACTED rows + bias + head-major scatter
// ---------------------------------------------------------------------------
__global__ void __launch_bounds__(256) qkv_kernel(
    const float* __restrict__ bq, const float* __restrict__ bk,
    const float* __restrict__ bv) {
    const int nrows = g_nrows;
    const int bm = blockIdx.y * 128;
    if (bm >= nrows) return;
    const int z = blockIdx.z;
    const float* W    = (z == 0) ? g_Wqr : (z == 1) ? g_Wkr : g_Wvr;
    const float* bias = (z == 0) ? bq : (z == 1) ? bk : bv;
    float* out        = (z == 0) ? g_q : (z == 1) ? g_k : g_v;
    const int bn = blockIdx.x * 128;
    ca_tn(D_,
        [&](int r, int k) {
            int idx = bm + r;
            int m = g_rowidx[idx < nrows ? idx : 0];
            return g_xr + (size_t)m * D_ + k;
        },
        [&](int r, int k) { return W + (size_t)(bn + r) * D_ + k; },
        [&](int il, int jl, float v) {
            int idx = bm + il;
            if (idx >= nrows) return;
            int m = g_rowidx[idx], n = bn + jl;
            int b = m >> 9, s = m & 511;
            int h = n >> 7, d = n & 127;
            out[((size_t)((b * H_ + h) * S_ + s)) * DP_ + d] = rtf(v + bias[n]);
        });
}

// ---------------------------------------------------------------------------
// 2) RNN input GEMMs
// ---------------------------------------------------------------------------
__device__ __forceinline__ const float* feats_row(int rr) {
    int f = rr >> 14;
    int rem = rr & 16383;
    int bh4 = rem >> 9;
    int s   = rem & 511;
    int b = bh4 >> 2, hh = bh4 & 3;
    const float* src = (f == 0) ? g_q : (f == 1) ? g_k : g_v;
    return src + ((size_t)((b * H_ + 4 + hh) * S_ + s)) * DP_;
}

__global__ void __launch_bounds__(256) rnn_in_kernel(
    const float* __restrict__ bih_f, const float* __restrict__ bih_b) {
    const int z = blockIdx.z;
    const float* W    = z ? g_Wihbr : g_Wihfr;
    const float* bias = z ? bih_b : bih_f;
    float* dst        = z ? g_Bm : g_A;
    const int bm = blockIdx.y * 128;
    ca_tn(DP_,
        [&](int r, int k) { return feats_row(bm + r) + k; },
        [&](int r, int k) { return W + (size_t)r * DP_ + k; },
        [&](int il, int jl, float v) {
            dst[(size_t)(bm + il) * DP_ + jl] = v + bias[jl];
        });
}

// ---------------------------------------------------------------------------
// 3) First RNN step (elementwise; rounded out -- H1 feeds GEMMs)
// ---------------------------------------------------------------------------
__global__ void rnn_h1_kernel(const float* __restrict__ bih_f,
                              const float* __restrict__ bhh_f,
                              const float* __restrict__ bhh_b) {
    int gid = blockIdx.x * blockDim.x + threadIdx.x;
    if (gid >= NR_ * DP_) return;
    int r = gid >> 7, d = gid & 127;
    int s = r & 511;
    float af = s ? g_A[gid - DP_] : bih_f[d];
    g_H1f[gid] = rtf(tanhf(af + bhh_f[d]));
    g_H1b[gid] = rtf(tanhf(g_Bm[gid] + bhh_b[d]));
}

// ---------------------------------------------------------------------------
// 4) Forward step 2:  Yf = tanh( A + H1f@Whh_f^T + bhh_f )
// ---------------------------------------------------------------------------
__global__ void __launch_bounds__(256) rnn_h2f_kernel(const float* __restrict__ bhh_f) {
    const int bm = blockIdx.y * 128;
    ca_tn(DP_,
        [&](int r, int k) { return g_H1f + (size_t)(bm + r) * DP_ + k; },
        [&](int r, int k) { return g_Whhfr + (size_t)r * DP_ + k; },
        [&](int il, int jl, float v) {
            size_t idx = (size_t)(bm + il) * DP_ + jl;
            g_Yf[idx] = tanhf(v + g_A[idx] + bhh_f[jl]);
        });
}

// ---------------------------------------------------------------------------
// 5) Backward step 2 + combine + scatter back into q/k/v heads 4..7 (rounded)
// ---------------------------------------------------------------------------
__global__ void __launch_bounds__(256) rnn_h2b_kernel(
    const float* __restrict__ bih_b, const float* __restrict__ bhh_b) {
    const int bm = blockIdx.y * 128;
    ca_tn(DP_,
        [&](int r, int k) { return g_H1b + (size_t)(bm + r) * DP_ + k; },
        [&](int r, int k) { return g_Whhbr + (size_t)r * DP_ + k; },
        [&](int il, int jl, float v) {
            int m = bm + il, n = jl;
            int s = m & 511;
            float shiftB = s ? g_Bm[(size_t)(m - 1) * DP_ + n] : bih_b[n];
            float y = g_Yf[(size_t)m * DP_ + n] + tanhf(v + shiftB + bhh_b[n]);
            int f = m >> 14, rem = m & 16383, bh4 = rem >> 9;
            int b = bh4 >> 2, hh = bh4 & 3;
            float* dst = (f == 0) ? g_q : (f == 1) ? g_k : g_v;
            dst[((size_t)((b * H_ + 4 + hh) * S_ + s)) * DP_ + n] = rtf(y);
        });
}

// ---------------------------------------------------------------------------
// 6) P[row,j] = (q[row] . rel_emb[j]) / SCALE
// ---------------------------------------------------------------------------
__global__ void p_kernel(const float* __restrict__ rel_emb) {
    int gid = blockIdx.x * blockDim.x + threadIdx.x;
    if (gid >= ROWS_ * 65) return;
    int row = gid / 65, j = gid - row * 65;
    const float* qr = g_q + (size_t)row * DP_;
    const float* er = rel_emb + (size_t)j * DP_;
    float s = 0.f;
#pragma unroll 8
    for (int d = 0; d < DP_; d++) s = fmaf(qr[d], er[d], s);
    g_P[gid] = s * INV_SCALE;
}

// ---------------------------------------------------------------------------
// 7) scores (pre-softmax) into the attn buffer
// ---------------------------------------------------------------------------
__global__ void __launch_bounds__(256) scores_kernel(float* __restrict__ attn,
                                                     int attn_in_out) {
    float* ap = attn_in_out ? attn : g_attn_fb;
    const int z = blockIdx.z;
    const int b = z >> 3;
    const int bm = blockIdx.y * 128, bn = blockIdx.x * 128;
    const float* qb = g_q + (size_t)z * S_ * DP_;
    const float* kb = g_k + (size_t)z * S_ * DP_;
    ca_tn(DP_,
        [&](int r, int k) { return qb + (size_t)(bm + r) * DP_ + k; },
        [&](int r, int k) { return kb + (size_t)(bn + r) * DP_ + k; },
        [&](int il, int jl, float v) {
            int qi = bm + il, ki = bn + jl;
            float val;
            if (g_mask[b * S_ + ki]) {
                val = -1e18f;
            } else {
                int off = ki - qi;
                off = off < -32 ? -32 : (off > 32 ? 32 : off);
                val = v * INV_SCALE + g_P[((size_t)z * S_ + qi) * 65 + off + 32];
            }
            ap[(size_t)z * S_ * S_ + (size_t)qi * S_ + ki] = val;
        });
}

// ---------------------------------------------------------------------------
// 8) Softmax per row + bucketed rel sums R
// ---------------------------------------------------------------------------
__device__ __forceinline__ float blk_reduce(float v, float* red, bool is_max) {
#pragma unroll
    for (int o = 16; o > 0; o >>= 1) {
        float w = __shfl_xor_sync(0xffffffffu, v, o);
        v = is_max ? fmaxf(v, w) : (v + w);
    }
    int warp = threadIdx.x >> 5, lane = threadIdx.x & 31;
    if (lane == 0) red[warp] = v;
    __syncthreads();
    float r = red[0];
#pragma unroll
    for (int i = 1; i < 8; i++) r = is_max ? fmaxf(r, red[i]) : (r + red[i]);
    __syncthreads();
    return r;
}

__global__ void __launch_bounds__(256) softmax_kernel(float* __restrict__ attn,
                                                      int attn_in_out) {
    float* ap = attn_in_out ? attn : g_attn_fb;
    int row = blockIdx.x;
    int q = row & 511;
    float* p = ap + (size_t)row * S_;
    __shared__ float sh[S_];
    __shared__ float red[8];
    int t = threadIdx.x;
    float v0 = p[t], v1 = p[t + 256];
    float mx = blk_reduce(fmaxf(v0, v1), red, true);
    float e0 = expf(v0 - mx), e1 = expf(v1 - mx);
    float sum = blk_reduce(e0 + e1, red, false);
    float inv = 1.f / sum;
    e0 *= inv; e1 *= inv;
    p[t] = e0; p[t + 256] = e1;
    sh[t] = e0; sh[t + 256] = e1;
    float r0 = 0.f, r64 = 0.f;
    if (t <= q - 32)        r0  += e0;
    if (t >= q + 32)        r64 += e0;
    if (t + 256 <= q - 32)  r0  += e1;
    if (t + 256 >= q + 32)  r64 += e1;
    r0  = blk_reduce(r0,  red, false);
    r64 = blk_reduce(r64, red, false);
    float* Rr = g_R + (size_t)row * 65;
    if (t == 0) { Rr[0] = r0; Rr[64] = r64; }
    if (t >= 1 && t <= 63) {
        int k = q + t - 32;
        Rr[t] = (k >= 0 && k < S_) ? sh[k] : 0.f;
    }
}

// ---------------------------------------------------------------------------
// 9) ctx = attn @ v  (NN, per bh)
// ---------------------------------------------------------------------------
__global__ void __launch_bounds__(256) ctx_kernel(const float* __restrict__ attn,
                                                  int attn_in_out) {
    const float* ap = attn_in_out ? attn : g_attn_fb;
    const int z = blockIdx.z;
    const int bm = blockIdx.y * 128;
    const float* Ab = ap + (size_t)z * S_ * S_;
    const float* Vb = g_v + (size_t)z * S_ * DP_;
    ca_nn(S_,
        [&](int r, int k) { return Ab + (size_t)(bm + r) * S_ + k; },
        [&](int k, int n) { return Vb + (size_t)k * DP_ + n; },
        [&](int il, int jl, float v) {
            g_ctx[(size_t)z * S_ * DP_ + (size_t)(bm + il) * DP_ + jl] = v;
        });
}

// ---------------------------------------------------------------------------
// 10) ctx += R @ rel_emb  (rounded out -- feeds out GEMM)
// ---------------------------------------------------------------------------
__global__ void ctx_rel_kernel(const float* __restrict__ rel_emb) {
    int gid = blockIdx.x * blockDim.x + threadIdx.x;
    if (gid >= ROWS_ * DP_) return;
    int row = gid >> 7, d = gid & 127;
    const float* Rr = g_R + (size_t)row * 65;
    float s = 0.f;
#pragma unroll
    for (int j = 0; j < 65; j++) s = fmaf(Rr[j], rel_emb[(size_t)j * DP_ + d], s);
    g_ctx[gid] = rtf(g_ctx[gid] + s);
}

// ---------------------------------------------------------------------------
// 11) out = ctx_perm @ Wo^T + bo
// ---------------------------------------------------------------------------
__global__ void __launch_bounds__(256) out_kernel(const float* __restrict__ bo,
                                                  float* __restrict__ out) {
    const int bm = blockIdx.y * 128, bn = blockIdx.x * 128;
    ca_tn(D_,
        [&](int r, int k) {
            int m = bm + r;
            int b = m >> 9, s = m & 511;
            int h = k >> 7, d = k & 127;
            return g_ctx + ((size_t)((b * H_ + h) * S_ + s)) * DP_ + d;
        },
        [&](int r, int k) { return g_Wor + (size_t)(bn + r) * D_ + k; },
        [&](int il, int jl, float v) {
            int m = bm + il, n = bn + jl;
            out[(size_t)m * D_ + n] = v + bo[n];
        });
}

// ---------------------------------------------------------------------------
// Host launcher
// ---------------------------------------------------------------------------
extern "C" void kernel_launch(void* const* d_in, const int* in_sizes, int n_in,
                              void* d_out, int out_size) {
    const float* x     = (const float*)d_in[0];
    const void*  mask  = d_in[1];
    const float* Wq    = (const float*)d_in[2];
    const float* bq    = (const float*)d_in[3];
    const float* Wk    = (const float*)d_in[4];
    const float* bk    = (const float*)d_in[5];
    const float* Wv    = (const float*)d_in[6];
    const float* bv    = (const float*)d_in[7];
    const float* Wo    = (const float*)d_in[8];
    const float* bo    = (const float*)d_in[9];
    const float* rel   = (const float*)d_in[10];
    const float* Wih_f = (const float*)d_in[11];
    const float* Whh_f = (const float*)d_in[12];
    const float* bih_f = (const float*)d_in[13];
    const float* bhh_f = (const float*)d_in[14];
    const float* Wih_b = (const float*)d_in[15];
    const float* Whh_b = (const float*)d_in[16];
    const float* bih_b = (const float*)d_in[17];
    const float* bhh_b = (const float*)d_in[18];

    float* out = (float*)d_out;
    const int attn_in_out = (out_size >= NOUT_ + BH_ * S_ * S_) ? 1 : 0;
    float* attn = attn_in_out ? (out + NOUT_) : nullptr;

    static int smem_set = 0;
    if (!smem_set) {
        cudaFuncSetAttribute(qkv_kernel,     cudaFuncAttributeMaxDynamicSharedMemorySize, SMEM_TN);
        cudaFuncSetAttribute(rnn_in_kernel,  cudaFuncAttributeMaxDynamicSharedMemorySize, SMEM_TN);
        cudaFuncSetAttribute(rnn_h2f_kernel, cudaFuncAttributeMaxDynamicSharedMemorySize, SMEM_TN);
        cudaFuncSetAttribute(rnn_h2b_kernel, cudaFuncAttributeMaxDynamicSharedMemorySize, SMEM_TN);
        cudaFuncSetAttribute(scores_kernel,  cudaFuncAttributeMaxDynamicSharedMemorySize, SMEM_TN);
        cudaFuncSetAttribute(ctx_kernel,     cudaFuncAttributeMaxDynamicSharedMemorySize, SMEM_NN);
        cudaFuncSetAttribute(out_kernel,     cudaFuncAttributeMaxDynamicSharedMemorySize, SMEM_TN);
        smem_set = 1;
    }

    // tf32 pre-rounding (rna) of all GEMM operand tensors
    auto rnd = [&](const float* src, float* dst, int n) {
        round_kernel<<<(n / 4 + 255) / 256, 256>>>((const float4*)src, (float4*)dst, n / 4);
    };
    float* p_xr;  cudaGetSymbolAddress((void**)&p_xr,  g_xr);
    float* p_wq;  cudaGetSymbolAddress((void**)&p_wq,  g_Wqr);
    float* p_wk;  cudaGetSymbolAddress((void**)&p_wk,  g_Wkr);
    float* p_wv;  cudaGetSymbolAddress((void**)&p_wv,  g_Wvr);
    float* p_wo;  cudaGetSymbolAddress((void**)&p_wo,  g_Wor);
    float* p_wif; cudaGetSymbolAddress((void**)&p_wif, g_Wihfr);
    float* p_whf; cudaGetSymbolAddress((void**)&p_whf, g_Whhfr);
    float* p_wib; cudaGetSymbolAddress((void**)&p_wib, g_Wihbr);
    float* p_whb; cudaGetSymbolAddress((void**)&p_whb, g_Whhbr);
    rnd(x, p_xr, MS_ * D_);
    rnd(Wq, p_wq, D_ * D_);
    rnd(Wk, p_wk, D_ * D_);
    rnd(Wv, p_wv, D_ * D_);
    rnd(Wo, p_wo, D_ * D_);
    rnd(Wih_f, p_wif, DP_ * DP_);
    rnd(Whh_f, p_whf, DP_ * DP_);
    rnd(Wih_b, p_wib, DP_ * DP_);
    rnd(Whh_b, p_whb, DP_ * DP_);

    mask_norm_kernel<<<1, 1024>>>(mask);

    // zero-fill masked rows, then compute only unmasked rows
    zero_masked_kernel<<<(MS_ * D_ + 255) / 256, 256>>>();
    qkv_kernel<<<dim3(D_ / 128, MS_ / 128, 3), 256, SMEM_TN>>>(bq, bk, bv);

    rnn_in_kernel<<<dim3(1, NR_ / 128, 2), 256, SMEM_TN>>>(bih_f, bih_b);
    rnn_h1_kernel<<<(NR_ * DP_) / 256, 256>>>(bih_f, bhh_f, bhh_b);
    rnn_h2f_kernel<<<dim3(1, NR_ / 128), 256, SMEM_TN>>>(bhh_f);
    rnn_h2b_kernel<<<dim3(1, NR_ / 128), 256, SMEM_TN>>>(bih_b, bhh_b);

    p_kernel<<<(ROWS_ * 65 + 255) / 256, 256>>>(rel);

    scores_kernel<<<dim3(S_ / 128, S_ / 128, BH_), 256, SMEM_TN>>>(attn, attn_in_out);
    softmax_kernel<<<ROWS_, 256>>>(attn, attn_in_out);
    ctx_kernel<<<dim3(1, S_ / 128, BH_), 256, SMEM_NN>>>(attn, attn_in_out);
    ctx_rel_kernel<<<(ROWS_ * DP_) / 256, 256>>>(rel);
    out_kernel<<<dim3(D_ / 128, MS_ / 128), 256, SMEM_TN>>>(bo, out);
}

// round 13
// speedup vs baseline: 2.5740x; 2.2535x over previous
#include <cuda_runtime.h>
#include <cstdint>
#include <math.h>

// ---------------------------------------------------------------------------
// Problem constants
// ---------------------------------------------------------------------------
namespace {
constexpr int B_   = 8;
constexpr int S_   = 512;
constexpr int D_   = 1024;
constexpr int H_   = 8;
constexpr int DP_  = 128;              // head dim
constexpr int BH_  = B_ * H_;          // 64
constexpr int MS_  = B_ * S_;          // 4096  (rows of x)
constexpr int NR_  = 96 * S_;          // 49152 RNN rows
constexpr int ROWS_ = BH_ * S_;        // 32768 (b,h,q) rows
constexpr int NOUT_ = MS_ * D_;        // 4194304 elements of `out`
constexpr float INV_SCALE = 0.08838834764831845f;  // 1/sqrt(128)
// smem: A[3][128][20] + B_tn[3][128][20]  /  B_nn[3][16][136]
constexpr int SMEM_TN = (3 * 128 * 20 + 3 * 128 * 20) * 4;   // 61440
constexpr int SMEM_NN = (3 * 128 * 20 + 3 * 16 * 136) * 4;   // 56832
}

// ---------------------------------------------------------------------------
// Scratch (static device globals -- no runtime allocation allowed)
// ---------------------------------------------------------------------------
__device__ float g_q  [BH_ * S_ * DP_];
__device__ float g_k  [BH_ * S_ * DP_];
__device__ float g_v  [BH_ * S_ * DP_];
__device__ float g_ctx[BH_ * S_ * DP_];
__device__ float g_A  [NR_ * DP_];
__device__ float g_Bm [NR_ * DP_];
__device__ float g_H1f[NR_ * DP_];
__device__ float g_H1b[NR_ * DP_];
__device__ float g_Yf [NR_ * DP_];
__device__ float g_P  [ROWS_ * 65];
__device__ float g_R  [ROWS_ * 65];
__device__ int   g_mask[MS_];
__device__ int   g_rowidx[MS_];        // compacted unmasked row indices
__device__ int   g_nrows;              // number of unmasked rows
__device__ float g_attn_fb[(size_t)BH_ * S_ * S_];
// tf32-rounded operand copies
__device__ float g_xr  [MS_ * D_];
__device__ float g_Wqr [D_ * D_];
__device__ float g_Wkr [D_ * D_];
__device__ float g_Wvr [D_ * D_];
__device__ float g_Wor [D_ * D_];
__device__ float g_Wihfr[DP_ * DP_];
__device__ float g_Whhfr[DP_ * DP_];
__device__ float g_Wihbr[DP_ * DP_];
__device__ float g_Whhbr[DP_ * DP_];
__device__ float g_relr [65 * DP_];

// ---------------------------------------------------------------------------
// tf32 / cp.async helpers
// ---------------------------------------------------------------------------
__device__ __forceinline__ unsigned f2tf(float x) {
    unsigned r;
    asm("cvt.rna.tf32.f32 %0, %1;" : "=r"(r) : "f"(x));
    return r;
}
__device__ __forceinline__ float rtf(float x) { return __uint_as_float(f2tf(x)); }

__device__ __forceinline__ void mma_tf32(float* d, const unsigned* a, const unsigned* b) {
    asm volatile(
        "mma.sync.aligned.m16n8k8.row.col.f32.tf32.tf32.f32 "
        "{%0,%1,%2,%3}, {%4,%5,%6,%7}, {%8,%9}, {%0,%1,%2,%3};\n"
        : "+f"(d[0]), "+f"(d[1]), "+f"(d[2]), "+f"(d[3])
        : "r"(a[0]), "r"(a[1]), "r"(a[2]), "r"(a[3]), "r"(b[0]), "r"(b[1]));
}

__device__ __forceinline__ void cp16(void* s, const void* g) {
    unsigned a = (unsigned)__cvta_generic_to_shared(s);
    asm volatile("cp.async.cg.shared.global [%0], [%1], 16;" :: "r"(a), "l"(g));
}
__device__ __forceinline__ void cp_commit() { asm volatile("cp.async.commit_group;"); }
__device__ __forceinline__ void cp_wait1()  { asm volatile("cp.async.wait_group 1;"); }

// ---------------------------------------------------------------------------
// 128x128 tf32 MMA cores with cp.async 3-stage pipeline (R7 proven core).
// 256 threads = 8 warps (2M x 4N), warp tile 64x32.
// ---------------------------------------------------------------------------
template <class FA, class FB, class FC>
__device__ __forceinline__ void ca_tn(int K, FA rowA, FB rowB, FC storeC) {
    extern __shared__ unsigned sm_[];
    unsigned (*As)[128][20] = reinterpret_cast<unsigned(*)[128][20]>(sm_);
    unsigned (*Bs)[128][20] = reinterpret_cast<unsigned(*)[128][20]>(sm_ + 3 * 128 * 20);
    const int tid  = threadIdx.x;
    const int lane = tid & 31, warp = tid >> 5;
    const int la3  = lane & 3, lg = lane >> 2;
    const int wm   = (warp & 1) * 64, wn = (warp >> 1) * 32;
    const int lr   = tid >> 2, lc = (tid & 3) * 4;
    float acc[4][4][4] = {};
    const int nk = K / 16;
    auto issue = [&](int st, int k0) {
        cp16(&As[st][lr][lc],      rowA(lr,      k0 + lc));
        cp16(&As[st][lr + 64][lc], rowA(lr + 64, k0 + lc));
        cp16(&Bs[st][lr][lc],      rowB(lr,      k0 + lc));
        cp16(&Bs[st][lr + 64][lc], rowB(lr + 64, k0 + lc));
    };
    issue(0, 0);  cp_commit();
    issue(1, 16); cp_commit();
    int st = 0;
    for (int it = 0; it < nk; it++) {
        cp_wait1();
        __syncthreads();
        if (it + 2 < nk) {
            int ns = st + 2; if (ns >= 3) ns -= 3;
            issue(ns, (it + 2) * 16);
        }
        cp_commit();
#pragma unroll
        for (int kc = 0; kc < 16; kc += 8) {
            unsigned af[4][4], bf[4][2];
#pragma unroll
            for (int mi = 0; mi < 4; mi++) {
                int m0 = wm + 16 * mi;
                af[mi][0] = As[st][m0 + lg][kc + la3];
                af[mi][1] = As[st][m0 + 8 + lg][kc + la3];
                af[mi][2] = As[st][m0 + lg][kc + 4 + la3];
                af[mi][3] = As[st][m0 + 8 + lg][kc + 4 + la3];
            }
#pragma unroll
            for (int nj = 0; nj < 4; nj++) {
                int n0 = wn + 8 * nj;
                bf[nj][0] = Bs[st][n0 + lg][kc + la3];
                bf[nj][1] = Bs[st][n0 + lg][kc + 4 + la3];
            }
#pragma unroll
            for (int mi = 0; mi < 4; mi++)
#pragma unroll
                for (int nj = 0; nj < 4; nj++) mma_tf32(acc[mi][nj], af[mi], bf[nj]);
        }
        if (++st == 3) st = 0;
    }
#pragma unroll
    for (int mi = 0; mi < 4; mi++)
#pragma unroll
        for (int nj = 0; nj < 4; nj++) {
            int r = wm + 16 * mi + lg, c = wn + 8 * nj + 2 * la3;
            storeC(r,     c,     acc[mi][nj][0]);
            storeC(r,     c + 1, acc[mi][nj][1]);
            storeC(r + 8, c,     acc[mi][nj][2]);
            storeC(r + 8, c + 1, acc[mi][nj][3]);
        }
}

template <class FA, class FB, class FC>
__device__ __forceinline__ void ca_nn(int K, FA rowA, FB rowB, FC storeC) {
    extern __shared__ unsigned sm_[];
    unsigned (*As)[128][20] = reinterpret_cast<unsigned(*)[128][20]>(sm_);
    unsigned (*Bs)[16][136] = reinterpret_cast<unsigned(*)[16][136]>(sm_ + 3 * 128 * 20);
    const int tid  = threadIdx.x;
    const int lane = tid & 31, warp = tid >> 5;
    const int la3  = lane & 3, lg = lane >> 2;
    const int wm   = (warp & 1) * 64, wn = (warp >> 1) * 32;
    const int lr   = tid >> 2, lc = (tid & 3) * 4;
    const int br   = tid >> 5, bc = (tid & 31) * 4;
    float acc[4][4][4] = {};
    const int nk = K / 16;
    auto issue = [&](int st, int k0) {
        cp16(&As[st][lr][lc],      rowA(lr,      k0 + lc));
        cp16(&As[st][lr + 64][lc], rowA(lr + 64, k0 + lc));
        cp16(&Bs[st][br][bc],      rowB(k0 + br,     bc));
        cp16(&Bs[st][br + 8][bc],  rowB(k0 + br + 8, bc));
    };
    issue(0, 0);  cp_commit();
    issue(1, 16); cp_commit();
    int st = 0;
    for (int it = 0; it < nk; it++) {
        cp_wait1();
        __syncthreads();
        if (it + 2 < nk) {
            int ns = st + 2; if (ns >= 3) ns -= 3;
            issue(ns, (it + 2) * 16);
        }
        cp_commit();
#pragma unroll
        for (int kc = 0; kc < 16; kc += 8) {
            unsigned af[4][4], bf[4][2];
#pragma unroll
            for (int mi = 0; mi < 4; mi++) {
                int m0 = wm + 16 * mi;
                af[mi][0] = As[st][m0 + lg][kc + la3];
                af[mi][1] = As[st][m0 + 8 + lg][kc + la3];
                af[mi][2] = As[st][m0 + lg][kc + 4 + la3];
                af[mi][3] = As[st][m0 + 8 + lg][kc + 4 + la3];
            }
#pragma unroll
            for (int nj = 0; nj < 4; nj++) {
                int n0 = wn + 8 * nj;
                bf[nj][0] = Bs[st][kc + la3][n0 + lg];
                bf[nj][1] = Bs[st][kc + 4 + la3][n0 + lg];
            }
#pragma unroll
            for (int mi = 0; mi < 4; mi++)
#pragma unroll
                for (int nj = 0; nj < 4; nj++) mma_tf32(acc[mi][nj], af[mi], bf[nj]);
        }
        if (++st == 3) st = 0;
    }
#pragma unroll
    for (int mi = 0; mi < 4; mi++)
#pragma unroll
        for (int nj = 0; nj < 4; nj++) {
            int r = wm + 16 * mi + lg, c = wn + 8 * nj + 2 * la3;
            storeC(r,     c,     acc[mi][nj][0]);
            storeC(r,     c + 1, acc[mi][nj][1]);
            storeC(r + 8, c,     acc[mi][nj][2]);
            storeC(r + 8, c + 1, acc[mi][nj][3]);
        }
}

// ---------------------------------------------------------------------------
// tf32 pre-rounding of GEMM operands (rna, once)
// ---------------------------------------------------------------------------
__global__ void round_kernel(const float4* __restrict__ src, float4* __restrict__ dst, int n4) {
    int i = blockIdx.x * blockDim.x + threadIdx.x;
    if (i >= n4) return;
    float4 v = src[i];
    v.x = rtf(v.x); v.y = rtf(v.y); v.z = rtf(v.z); v.w = rtf(v.w);
    dst[i] = v;
}

// batched variant: y selects one of 4 (src,dst) pairs (all same n4)
__global__ void round4_kernel(const float4* s0, float4* d0,
                              const float4* s1, float4* d1,
                              const float4* s2, float4* d2,
                              const float4* s3, float4* d3, int n4) {
    int i = blockIdx.x * blockDim.x + threadIdx.x;
    if (i >= n4) return;
    const float4* s; float4* d;
    switch (blockIdx.y) {
        case 0: s = s0; d = d0; break;
        case 1: s = s1; d = d1; break;
        case 2: s = s2; d = d2; break;
        default: s = s3; d = d3; break;
    }
    float4 v = s[i];
    v.x = rtf(v.x); v.y = rtf(v.y); v.z = rtf(v.z); v.w = rtf(v.w);
    d[i] = v;
}

// ---------------------------------------------------------------------------
// 0) Mask normalization + row compaction (single block)
// ---------------------------------------------------------------------------
__global__ void mask_norm_kernel(const void* raw) {
    __shared__ int f_int, f_flt;
    const unsigned int* w = (const unsigned int*)raw;
    int t = threadIdx.x;  // 1024 threads
    if (t == 0) { f_int = 1; f_flt = 1; g_nrows = 0; }
    __syncthreads();
    unsigned int x = w[t];
    if (x != 0u && x != 1u) f_int = 0;
    if (x != 0u && x != 0x3F800000u) f_flt = 0;
    __syncthreads();
    if (f_int) {
        for (int i = t; i < MS_; i += 1024) g_mask[i] = (int)w[i];
    } else if (f_flt) {
        const float* f = (const float*)raw;
        for (int i = t; i < MS_; i += 1024) g_mask[i] = (f[i] != 0.f);
    } else {
        const unsigned char* bts = (const unsigned char*)raw;
        for (int i = t; i < MS_; i += 1024) g_mask[i] = (bts[i] != 0);
    }
    __syncthreads();
    for (int i = t; i < MS_; i += 1024) {
        if (!g_mask[i]) {
            int pos = atomicAdd(&g_nrows, 1);
            g_rowidx[pos] = i;
        }
    }
}

// ---------------------------------------------------------------------------
// 0b) Zero-fill q/k/v for masked rows (their GEMM result is skipped)
// ---------------------------------------------------------------------------
__global__ void zero_masked_kernel() {
    int i = blockIdx.x * 256 + threadIdx.x;
    if (i >= MS_ * D_) return;
    int m = i >> 10;
    if (!g_mask[m]) return;
    int n = i & 1023;
    int b = m >> 9, s = m & 511;
    int h = n >> 7, d = n & 127;
    size_t off = ((size_t)((b * H_ + h) * S_ + s)) * DP_ + d;
    g_q[off] = 0.f; g_k[off] = 0.f; g_v[off] = 0.f;
}

// ---------------------------------------------------------------------------
// 1) QKV projections on COMPACTED rows + bias + head-major scatter
// ---------------------------------------------------------------------------
__global__ void __launch_bounds__(256) qkv_kernel(
    const float* __restrict__ bq, const float* __restrict__ bk,
    const float* __restrict__ bv) {
    const int nrows = g_nrows;
    const int bm = blockIdx.y * 128;
    if (bm >= nrows) return;
    const int z = blockIdx.z;
    const float* W    = (z == 0) ? g_Wqr : (z == 1) ? g_Wkr : g_Wvr;
    const float* bias = (z == 0) ? bq : (z == 1) ? bk : bv;
    float* out        = (z == 0) ? g_q : (z == 1) ? g_k : g_v;
    const int bn = blockIdx.x * 128;
    ca_tn(D_,
        [&](int r, int k) {
            int idx = bm + r;
            int m = g_rowidx[idx < nrows ? idx : 0];
            return g_xr + (size_t)m * D_ + k;
        },
        [&](int r, int k) { return W + (size_t)(bn + r) * D_ + k; },
        [&](int il, int jl, float v) {
            int idx = bm + il;
            if (idx >= nrows) return;
            int m = g_rowidx[idx], n = bn + jl;
            int b = m >> 9, s = m & 511;
            int h = n >> 7, d = n & 127;
            out[((size_t)((b * H_ + h) * S_ + s)) * DP_ + d] = rtf(v + bias[n]);
        });
}

// ---------------------------------------------------------------------------
// 2) RNN input GEMMs
// ---------------------------------------------------------------------------
__device__ __forceinline__ const float* feats_row(int rr) {
    int f = rr >> 14;
    int rem = rr & 16383;
    int bh4 = rem >> 9;
    int s   = rem & 511;
    int b = bh4 >> 2, hh = bh4 & 3;
    const float* src = (f == 0) ? g_q : (f == 1) ? g_k : g_v;
    return src + ((size_t)((b * H_ + 4 + hh) * S_ + s)) * DP_;
}

__global__ void __launch_bounds__(256) rnn_in_kernel(
    const float* __restrict__ bih_f, const float* __restrict__ bih_b) {
    const int z = blockIdx.z;
    const float* W    = z ? g_Wihbr : g_Wihfr;
    const float* bias = z ? bih_b : bih_f;
    float* dst        = z ? g_Bm : g_A;
    const int bm = blockIdx.y * 128;
    ca_tn(DP_,
        [&](int r, int k) { return feats_row(bm + r) + k; },
        [&](int r, int k) { return W + (size_t)r * DP_ + k; },
        [&](int il, int jl, float v) {
            dst[(size_t)(bm + il) * DP_ + jl] = v + bias[jl];
        });
}

// ---------------------------------------------------------------------------
// 3) First RNN step (elementwise; rounded out -- H1 feeds GEMMs)
// ---------------------------------------------------------------------------
__global__ void rnn_h1_kernel(const float* __restrict__ bih_f,
                              const float* __restrict__ bhh_f,
                              const float* __restrict__ bhh_b) {
    int gid = blockIdx.x * blockDim.x + threadIdx.x;
    if (gid >= NR_ * DP_) return;
    int r = gid >> 7, d = gid & 127;
    int s = r & 511;
    float af = s ? g_A[gid - DP_] : bih_f[d];
    g_H1f[gid] = rtf(tanhf(af + bhh_f[d]));
    g_H1b[gid] = rtf(tanhf(g_Bm[gid] + bhh_b[d]));
}

// ---------------------------------------------------------------------------
// 4) Forward step 2:  Yf = tanh( A + H1f@Whh_f^T + bhh_f )
// ---------------------------------------------------------------------------
__global__ void __launch_bounds__(256) rnn_h2f_kernel(const float* __restrict__ bhh_f) {
    const int bm = blockIdx.y * 128;
    ca_tn(DP_,
        [&](int r, int k) { return g_H1f + (size_t)(bm + r) * DP_ + k; },
        [&](int r, int k) { return g_Whhfr + (size_t)r * DP_ + k; },
        [&](int il, int jl, float v) {
            size_t idx = (size_t)(bm + il) * DP_ + jl;
            g_Yf[idx] = tanhf(v + g_A[idx] + bhh_f[jl]);
        });
}

// ---------------------------------------------------------------------------
// 5) Backward step 2 + combine + scatter back into q/k/v heads 4..7 (rounded)
// ---------------------------------------------------------------------------
__global__ void __launch_bounds__(256) rnn_h2b_kernel(
    const float* __restrict__ bih_b, const float* __restrict__ bhh_b) {
    const int bm = blockIdx.y * 128;
    ca_tn(DP_,
        [&](int r, int k) { return g_H1b + (size_t)(bm + r) * DP_ + k; },
        [&](int r, int k) { return g_Whhbr + (size_t)r * DP_ + k; },
        [&](int il, int jl, float v) {
            int m = bm + il, n = jl;
            int s = m & 511;
            float shiftB = s ? g_Bm[(size_t)(m - 1) * DP_ + n] : bih_b[n];
            float y = g_Yf[(size_t)m * DP_ + n] + tanhf(v + shiftB + bhh_b[n]);
            int f = m >> 14, rem = m & 16383, bh4 = rem >> 9;
            int b = bh4 >> 2, hh = bh4 & 3;
            float* dst = (f == 0) ? g_q : (f == 1) ? g_k : g_v;
            dst[((size_t)((b * H_ + 4 + hh) * S_ + s)) * DP_ + n] = rtf(y);
        });
}

// ---------------------------------------------------------------------------
// 6) P = (q . rel_emb^T)/SCALE as tf32 GEMM (M=32768, N=65 padded to 128)
// ---------------------------------------------------------------------------
__global__ void __launch_bounds__(256) p_gemm_kernel() {
    const int bm = blockIdx.y * 128;
    ca_tn(DP_,
        [&](int r, int k) { return g_q + (size_t)(bm + r) * DP_ + k; },
        [&](int r, int k) { return g_relr + (size_t)(r < 65 ? r : 64) * DP_ + k; },
        [&](int il, int jl, float v) {
            if (jl < 65) g_P[(size_t)(bm + il) * 65 + jl] = v * INV_SCALE;
        });
}

// ---------------------------------------------------------------------------
// 7) scores (pre-softmax) into the attn buffer
// ---------------------------------------------------------------------------
__global__ void __launch_bounds__(256) scores_kernel(float* __restrict__ attn,
                                                     int attn_in_out) {
    float* ap = attn_in_out ? attn : g_attn_fb;
    const int z = blockIdx.z;
    const int b = z >> 3;
    const int bm = blockIdx.y * 128, bn = blockIdx.x * 128;
    const float* qb = g_q + (size_t)z * S_ * DP_;
    const float* kb = g_k + (size_t)z * S_ * DP_;
    ca_tn(DP_,
        [&](int r, int k) { return qb + (size_t)(bm + r) * DP_ + k; },
        [&](int r, int k) { return kb + (size_t)(bn + r) * DP_ + k; },
        [&](int il, int jl, float v) {
            int qi = bm + il, ki = bn + jl;
            float val;
            if (g_mask[b * S_ + ki]) {
                val = -1e18f;
            } else {
                int off = ki - qi;
                off = off < -32 ? -32 : (off > 32 ? 32 : off);
                val = v * INV_SCALE + g_P[((size_t)z * S_ + qi) * 65 + off + 32];
            }
            ap[(size_t)z * S_ * S_ + (size_t)qi * S_ + ki] = val;
        });
}

// ---------------------------------------------------------------------------
// 8) Softmax per row + bucketed rel sums R
// ---------------------------------------------------------------------------
__device__ __forceinline__ float blk_reduce(float v, float* red, bool is_max) {
#pragma unroll
    for (int o = 16; o > 0; o >>= 1) {
        float w = __shfl_xor_sync(0xffffffffu, v, o);
        v = is_max ? fmaxf(v, w) : (v + w);
    }
    int warp = threadIdx.x >> 5, lane = threadIdx.x & 31;
    if (lane == 0) red[warp] = v;
    __syncthreads();
    float r = red[0];
#pragma unroll
    for (int i = 1; i < 8; i++) r = is_max ? fmaxf(r, red[i]) : (r + red[i]);
    __syncthreads();
    return r;
}

__global__ void __launch_bounds__(256) softmax_kernel(float* __restrict__ attn,
                                                      int attn_in_out) {
    float* ap = attn_in_out ? attn : g_attn_fb;
    int row = blockIdx.x;
    int q = row & 511;
    float* p = ap + (size_t)row * S_;
    __shared__ float sh[S_];
    __shared__ float red[8];
    int t = threadIdx.x;
    float v0 = p[t], v1 = p[t + 256];
    float mx = blk_reduce(fmaxf(v0, v1), red, true);
    float e0 = expf(v0 - mx), e1 = expf(v1 - mx);
    float sum = blk_reduce(e0 + e1, red, false);
    float inv = 1.f / sum;
    e0 *= inv; e1 *= inv;
    p[t] = e0; p[t + 256] = e1;
    sh[t] = e0; sh[t + 256] = e1;
    float r0 = 0.f, r64 = 0.f;
    if (t <= q - 32)        r0  += e0;
    if (t >= q + 32)        r64 += e0;
    if (t + 256 <= q - 32)  r0  += e1;
    if (t + 256 >= q + 32)  r64 += e1;
    r0  = blk_reduce(r0,  red, false);
    r64 = blk_reduce(r64, red, false);
    float* Rr = g_R + (size_t)row * 65;
    if (t == 0) { Rr[0] = r0; Rr[64] = r64; }
    if (t >= 1 && t <= 63) {
        int k = q + t - 32;
        Rr[t] = (k >= 0 && k < S_) ? sh[k] : 0.f;
    }
}

// ---------------------------------------------------------------------------
// 9) ctx = attn @ v  (NN, per bh)
// ---------------------------------------------------------------------------
__global__ void __launch_bounds__(256) ctx_kernel(const float* __restrict__ attn,
                                                  int attn_in_out) {
    const float* ap = attn_in_out ? attn : g_attn_fb;
    const int z = blockIdx.z;
    const int bm = blockIdx.y * 128;
    const float* Ab = ap + (size_t)z * S_ * S_;
    const float* Vb = g_v + (size_t)z * S_ * DP_;
    ca_nn(S_,
        [&](int r, int k) { return Ab + (size_t)(bm + r) * S_ + k; },
        [&](int k, int n) { return Vb + (size_t)k * DP_ + n; },
        [&](int il, int jl, float v) {
            g_ctx[(size_t)z * S_ * DP_ + (size_t)(bm + il) * DP_ + jl] = v;
        });
}

// ---------------------------------------------------------------------------
// 10) ctx += R @ rel_emb  (rounded out -- feeds out GEMM)
// ---------------------------------------------------------------------------
__global__ void ctx_rel_kernel(const float* __restrict__ rel_emb) {
    int gid = blockIdx.x * blockDim.x + threadIdx.x;
    if (gid >= ROWS_ * DP_) return;
    int row = gid >> 7, d = gid & 127;
    const float* Rr = g_R + (size_t)row * 65;
    float s = 0.f;
#pragma unroll
    for (int j = 0; j < 65; j++) s = fmaf(Rr[j], rel_emb[(size_t)j * DP_ + d], s);
    g_ctx[gid] = rtf(g_ctx[gid] + s);
}

// ---------------------------------------------------------------------------
// 11) out = ctx_perm @ Wo^T + bo
// ---------------------------------------------------------------------------
__global__ void __launch_bounds__(256) out_kernel(const float* __restrict__ bo,
                                                  float* __restrict__ out) {
    const int bm = blockIdx.y * 128, bn = blockIdx.x * 128;
    ca_tn(D_,
        [&](int r, int k) {
            int m = bm + r;
            int b = m >> 9, s = m & 511;
            int h = k >> 7, d = k & 127;
            return g_ctx + ((size_t)((b * H_ + h) * S_ + s)) * DP_ + d;
        },
        [&](int r, int k) { return g_Wor + (size_t)(bn + r) * D_ + k; },
        [&](int il, int jl, float v) {
            int m = bm + il, n = bn + jl;
            out[(size_t)m * D_ + n] = v + bo[n];
        });
}

// ---------------------------------------------------------------------------
// Host launcher
// ---------------------------------------------------------------------------
extern "C" void kernel_launch(void* const* d_in, const int* in_sizes, int n_in,
                              void* d_out, int out_size) {
    const float* x     = (const float*)d_in[0];
    const void*  mask  = d_in[1];
    const float* Wq    = (const float*)d_in[2];
    const float* bq    = (const float*)d_in[3];
    const float* Wk    = (const float*)d_in[4];
    const float* bk    = (const float*)d_in[5];
    const float* Wv    = (const float*)d_in[6];
    const float* bv    = (const float*)d_in[7];
    const float* Wo    = (const float*)d_in[8];
    const float* bo    = (const float*)d_in[9];
    const float* rel   = (const float*)d_in[10];
    const float* Wih_f = (const float*)d_in[11];
    const float* Whh_f = (const float*)d_in[12];
    const float* bih_f = (const float*)d_in[13];
    const float* bhh_f = (const float*)d_in[14];
    const float* Wih_b = (const float*)d_in[15];
    const float* Whh_b = (const float*)d_in[16];
    const float* bih_b = (const float*)d_in[17];
    const float* bhh_b = (const float*)d_in[18];

    float* out = (float*)d_out;
    const int attn_in_out = (out_size >= NOUT_ + BH_ * S_ * S_) ? 1 : 0;
    float* attn = attn_in_out ? (out + NOUT_) : nullptr;

    static int smem_set = 0;
    if (!smem_set) {
        cudaFuncSetAttribute(qkv_kernel,     cudaFuncAttributeMaxDynamicSharedMemorySize, SMEM_TN);
        cudaFuncSetAttribute(rnn_in_kernel,  cudaFuncAttributeMaxDynamicSharedMemorySize, SMEM_TN);
        cudaFuncSetAttribute(rnn_h2f_kernel, cudaFuncAttributeMaxDynamicSharedMemorySize, SMEM_TN);
        cudaFuncSetAttribute(rnn_h2b_kernel, cudaFuncAttributeMaxDynamicSharedMemorySize, SMEM_TN);
        cudaFuncSetAttribute(p_gemm_kernel,  cudaFuncAttributeMaxDynamicSharedMemorySize, SMEM_TN);
        cudaFuncSetAttribute(scores_kernel,  cudaFuncAttributeMaxDynamicSharedMemorySize, SMEM_TN);
        cudaFuncSetAttribute(ctx_kernel,     cudaFuncAttributeMaxDynamicSharedMemorySize, SMEM_NN);
        cudaFuncSetAttribute(out_kernel,     cudaFuncAttributeMaxDynamicSharedMemorySize, SMEM_TN);
        smem_set = 1;
    }

    // device pointers to rounded-copy buffers
    float* p_xr;  cudaGetSymbolAddress((void**)&p_xr,  g_xr);
    float* p_wq;  cudaGetSymbolAddress((void**)&p_wq,  g_Wqr);
    float* p_wk;  cudaGetSymbolAddress((void**)&p_wk,  g_Wkr);
    float* p_wv;  cudaGetSymbolAddress((void**)&p_wv,  g_Wvr);
    float* p_wo;  cudaGetSymbolAddress((void**)&p_wo,  g_Wor);
    float* p_wif; cudaGetSymbolAddress((void**)&p_wif, g_Wihfr);
    float* p_whf; cudaGetSymbolAddress((void**)&p_whf, g_Whhfr);
    float* p_wib; cudaGetSymbolAddress((void**)&p_wib, g_Wihbr);
    float* p_whb; cudaGetSymbolAddress((void**)&p_whb, g_Whhbr);
    float* p_rel; cudaGetSymbolAddress((void**)&p_rel, g_relr);

    // tf32 pre-rounding (rna): x, big weights (batched), rnn weights (batched), rel
    {
        int n4 = (MS_ * D_) / 4;
        round_kernel<<<(n4 + 255) / 256, 256>>>((const float4*)x, (float4*)p_xr, n4);
    }
    {
        int n4 = (D_ * D_) / 4;
        round4_kernel<<<dim3((n4 + 255) / 256, 4), 256>>>(
            (const float4*)Wq, (float4*)p_wq, (const float4*)Wk, (float4*)p_wk,
            (const float4*)Wv, (float4*)p_wv, (const float4*)Wo, (float4*)p_wo, n4);
    }
    {
        int n4 = (DP_ * DP_) / 4;
        round4_kernel<<<dim3((n4 + 255) / 256, 4), 256>>>(
            (const float4*)Wih_f, (float4*)p_wif, (const float4*)Whh_f, (float4*)p_whf,
            (const float4*)Wih_b, (float4*)p_wib, (const float4*)Whh_b, (float4*)p_whb, n4);
    }
    {
        int n4 = (65 * DP_) / 4;
        round_kernel<<<(n4 + 255) / 256, 256>>>((const float4*)rel, (float4*)p_rel, n4);
    }

    mask_norm_kernel<<<1, 1024>>>(mask);

    // zero-fill masked rows, then compute only unmasked rows
    zero_masked_kernel<<<(MS_ * D_ + 255) / 256, 256>>>();
    qkv_kernel<<<dim3(D_ / 128, MS_ / 128, 3), 256, SMEM_TN>>>(bq, bk, bv);

    rnn_in_kernel<<<dim3(1, NR_ / 128, 2), 256, SMEM_TN>>>(bih_f, bih_b);
    rnn_h1_kernel<<<(NR_ * DP_) / 256, 256>>>(bih_f, bhh_f, bhh_b);
    rnn_h2f_kernel<<<dim3(1, NR_ / 128), 256, SMEM_TN>>>(bhh_f);
    rnn_h2b_kernel<<<dim3(1, NR_ / 128), 256, SMEM_TN>>>(bih_b, bhh_b);

    p_gemm_kernel<<<dim3(1, ROWS_ / 128), 256, SMEM_TN>>>();

    scores_kernel<<<dim3(S_ / 128, S_ / 128, BH_), 256, SMEM_TN>>>(attn, attn_in_out);
    softmax_kernel<<<ROWS_, 256>>>(attn, attn_in_out);
    ctx_kernel<<<dim3(1, S_ / 128, BH_), 256, SMEM_NN>>>(attn, attn_in_out);
    ctx_rel_kernel<<<(ROWS_ * DP_) / 256, 256>>>(rel);
    out_kernel<<<dim3(D_ / 128, MS_ / 128), 256, SMEM_TN>>>(bo, out);
}

// round 16
// speedup vs baseline: 2.7802x; 1.0801x over previous
#include <cuda_runtime.h>
#include <cstdint>
#include <math.h>

// ---------------------------------------------------------------------------
// Problem constants
// ---------------------------------------------------------------------------
namespace {
constexpr int B_   = 8;
constexpr int S_   = 512;
constexpr int D_   = 1024;
constexpr int H_   = 8;
constexpr int DP_  = 128;              // head dim
constexpr int BH_  = B_ * H_;          // 64
constexpr int MS_  = B_ * S_;          // 4096  (rows of x)
constexpr int NR_  = 96 * S_;          // 49152 RNN rows
constexpr int ROWS_ = BH_ * S_;        // 32768 (b,h,q) rows
constexpr int NOUT_ = MS_ * D_;        // 4194304 elements of `out`
constexpr float INV_SCALE = 0.08838834764831845f;  // 1/sqrt(128)
constexpr int RK_  = 80;               // padded K for the R@rel GEMM
// smem: A[3][128][20] + B_tn[3][128][20]  /  B_nn[3][16][136]
constexpr int SMEM_TN = (3 * 128 * 20 + 3 * 128 * 20) * 4;   // 61440
constexpr int SMEM_NN = (3 * 128 * 20 + 3 * 16 * 136) * 4;   // 56832
}

// ---------------------------------------------------------------------------
// Scratch (static device globals -- no runtime allocation allowed)
// ---------------------------------------------------------------------------
__device__ float g_q  [BH_ * S_ * DP_];
__device__ float g_k  [BH_ * S_ * DP_];
__device__ float g_v  [BH_ * S_ * DP_];
__device__ float g_ctx[BH_ * S_ * DP_];
__device__ float g_A  [NR_ * DP_];
__device__ float g_Bm [NR_ * DP_];
__device__ float g_H1f[NR_ * DP_];
__device__ float g_H1b[NR_ * DP_];
__device__ float g_Yf [NR_ * DP_];
__device__ float g_P  [ROWS_ * 65];
__device__ float g_R  [ROWS_ * RK_];   // stride 80; cols 65..79 stay zero
__device__ int   g_mask[MS_];
__device__ int   g_rowidx[MS_];        // compacted unmasked row indices
__device__ int   g_nrows;              // number of unmasked rows
__device__ float g_attn_fb[(size_t)BH_ * S_ * S_];
// tf32-rounded operand copies
__device__ float g_xr  [MS_ * D_];
__device__ float g_Wqr [D_ * D_];
__device__ float g_Wkr [D_ * D_];
__device__ float g_Wvr [D_ * D_];
__device__ float g_Wor [D_ * D_];
__device__ float g_Wihfr[DP_ * DP_];
__device__ float g_Whhfr[DP_ * DP_];
__device__ float g_Wihbr[DP_ * DP_];
__device__ float g_Whhbr[DP_ * DP_];
__device__ float g_relr [65 * DP_];    // rounded rel (for P gemm, row-gather)
__device__ float g_relp [RK_ * DP_];   // rounded rel, K-padded (rows 65..79 zero)

// ---------------------------------------------------------------------------
// tf32 / cp.async helpers
// ---------------------------------------------------------------------------
__device__ __forceinline__ unsigned f2tf(float x) {
    unsigned r;
    asm("cvt.rna.tf32.f32 %0, %1;" : "=r"(r) : "f"(x));
    return r;
}
__device__ __forceinline__ float rtf(float x) { return __uint_as_float(f2tf(x)); }

__device__ __forceinline__ void mma_tf32(float* d, const unsigned* a, const unsigned* b) {
    asm volatile(
        "mma.sync.aligned.m16n8k8.row.col.f32.tf32.tf32.f32 "
        "{%0,%1,%2,%3}, {%4,%5,%6,%7}, {%8,%9}, {%0,%1,%2,%3};\n"
        : "+f"(d[0]), "+f"(d[1]), "+f"(d[2]), "+f"(d[3])
        : "r"(a[0]), "r"(a[1]), "r"(a[2]), "r"(a[3]), "r"(b[0]), "r"(b[1]));
}

__device__ __forceinline__ void cp16(void* s, const void* g) {
    unsigned a = (unsigned)__cvta_generic_to_shared(s);
    asm volatile("cp.async.cg.shared.global [%0], [%1], 16;" :: "r"(a), "l"(g));
}
__device__ __forceinline__ void cp_commit() { asm volatile("cp.async.commit_group;"); }
__device__ __forceinline__ void cp_wait1()  { asm volatile("cp.async.wait_group 1;"); }

// ---------------------------------------------------------------------------
// 128x128 tf32 MMA cores with cp.async 3-stage pipeline (R7 proven core).
// 256 threads = 8 warps (2M x 4N), warp tile 64x32.
// ---------------------------------------------------------------------------
template <class FA, class FB, class FC>
__device__ __forceinline__ void ca_tn(int K, FA rowA, FB rowB, FC storeC) {
    extern __shared__ unsigned sm_[];
    unsigned (*As)[128][20] = reinterpret_cast<unsigned(*)[128][20]>(sm_);
    unsigned (*Bs)[128][20] = reinterpret_cast<unsigned(*)[128][20]>(sm_ + 3 * 128 * 20);
    const int tid  = threadIdx.x;
    const int lane = tid & 31, warp = tid >> 5;
    const int la3  = lane & 3, lg = lane >> 2;
    const int wm   = (warp & 1) * 64, wn = (warp >> 1) * 32;
    const int lr   = tid >> 2, lc = (tid & 3) * 4;
    float acc[4][4][4] = {};
    const int nk = K / 16;
    auto issue = [&](int st, int k0) {
        cp16(&As[st][lr][lc],      rowA(lr,      k0 + lc));
        cp16(&As[st][lr + 64][lc], rowA(lr + 64, k0 + lc));
        cp16(&Bs[st][lr][lc],      rowB(lr,      k0 + lc));
        cp16(&Bs[st][lr + 64][lc], rowB(lr + 64, k0 + lc));
    };
    issue(0, 0);  cp_commit();
    issue(1, 16); cp_commit();
    int st = 0;
    for (int it = 0; it < nk; it++) {
        cp_wait1();
        __syncthreads();
        if (it + 2 < nk) {
            int ns = st + 2; if (ns >= 3) ns -= 3;
            issue(ns, (it + 2) * 16);
        }
        cp_commit();
#pragma unroll
        for (int kc = 0; kc < 16; kc += 8) {
            unsigned af[4][4], bf[4][2];
#pragma unroll
            for (int mi = 0; mi < 4; mi++) {
                int m0 = wm + 16 * mi;
                af[mi][0] = As[st][m0 + lg][kc + la3];
                af[mi][1] = As[st][m0 + 8 + lg][kc + la3];
                af[mi][2] = As[st][m0 + lg][kc + 4 + la3];
                af[mi][3] = As[st][m0 + 8 + lg][kc + 4 + la3];
            }
#pragma unroll
            for (int nj = 0; nj < 4; nj++) {
                int n0 = wn + 8 * nj;
                bf[nj][0] = Bs[st][n0 + lg][kc + la3];
                bf[nj][1] = Bs[st][n0 + lg][kc + 4 + la3];
            }
#pragma unroll
            for (int mi = 0; mi < 4; mi++)
#pragma unroll
                for (int nj = 0; nj < 4; nj++) mma_tf32(acc[mi][nj], af[mi], bf[nj]);
        }
        if (++st == 3) st = 0;
    }
#pragma unroll
    for (int mi = 0; mi < 4; mi++)
#pragma unroll
        for (int nj = 0; nj < 4; nj++) {
            int r = wm + 16 * mi + lg, c = wn + 8 * nj + 2 * la3;
            storeC(r,     c,     acc[mi][nj][0]);
            storeC(r,     c + 1, acc[mi][nj][1]);
            storeC(r + 8, c,     acc[mi][nj][2]);
            storeC(r + 8, c + 1, acc[mi][nj][3]);
        }
}

template <class FA, class FB, class FC>
__device__ __forceinline__ void ca_nn(int K, FA rowA, FB rowB, FC storeC) {
    extern __shared__ unsigned sm_[];
    unsigned (*As)[128][20] = reinterpret_cast<unsigned(*)[128][20]>(sm_);
    unsigned (*Bs)[16][136] = reinterpret_cast<unsigned(*)[16][136]>(sm_ + 3 * 128 * 20);
    const int tid  = threadIdx.x;
    const int lane = tid & 31, warp = tid >> 5;
    const int la3  = lane & 3, lg = lane >> 2;
    const int wm   = (warp & 1) * 64, wn = (warp >> 1) * 32;
    const int lr   = tid >> 2, lc = (tid & 3) * 4;
    const int br   = tid >> 5, bc = (tid & 31) * 4;
    float acc[4][4][4] = {};
    const int nk = K / 16;
    auto issue = [&](int st, int k0) {
        cp16(&As[st][lr][lc],      rowA(lr,      k0 + lc));
        cp16(&As[st][lr + 64][lc], rowA(lr + 64, k0 + lc));
        cp16(&Bs[st][br][bc],      rowB(k0 + br,     bc));
        cp16(&Bs[st][br + 8][bc],  rowB(k0 + br + 8, bc));
    };
    issue(0, 0);  cp_commit();
    issue(1, 16); cp_commit();
    int st = 0;
    for (int it = 0; it < nk; it++) {
        cp_wait1();
        __syncthreads();
        if (it + 2 < nk) {
            int ns = st + 2; if (ns >= 3) ns -= 3;
            issue(ns, (it + 2) * 16);
        }
        cp_commit();
#pragma unroll
        for (int kc = 0; kc < 16; kc += 8) {
            unsigned af[4][4], bf[4][2];
#pragma unroll
            for (int mi = 0; mi < 4; mi++) {
                int m0 = wm + 16 * mi;
                af[mi][0] = As[st][m0 + lg][kc + la3];
                af[mi][1] = As[st][m0 + 8 + lg][kc + la3];
                af[mi][2] = As[st][m0 + lg][kc + 4 + la3];
                af[mi][3] = As[st][m0 + 8 + lg][kc + 4 + la3];
            }
#pragma unroll
            for (int nj = 0; nj < 4; nj++) {
                int n0 = wn + 8 * nj;
                bf[nj][0] = Bs[st][kc + la3][n0 + lg];
                bf[nj][1] = Bs[st][kc + 4 + la3][n0 + lg];
            }
#pragma unroll
            for (int mi = 0; mi < 4; mi++)
#pragma unroll
                for (int nj = 0; nj < 4; nj++) mma_tf32(acc[mi][nj], af[mi], bf[nj]);
        }
        if (++st == 3) st = 0;
    }
#pragma unroll
    for (int mi = 0; mi < 4; mi++)
#pragma unroll
        for (int nj = 0; nj < 4; nj++) {
            int r = wm + 16 * mi + lg, c = wn + 8 * nj + 2 * la3;
            storeC(r,     c,     acc[mi][nj][0]);
            storeC(r,     c + 1, acc[mi][nj][1]);
            storeC(r + 8, c,     acc[mi][nj][2]);
            storeC(r + 8, c + 1, acc[mi][nj][3]);
        }
}

// ---------------------------------------------------------------------------
// tf32 pre-rounding of GEMM operands (rna, once)
// ---------------------------------------------------------------------------
__global__ void round_kernel(const float4* __restrict__ src, float4* __restrict__ dst, int n4) {
    int i = blockIdx.x * blockDim.x + threadIdx.x;
    if (i >= n4) return;
    float4 v = src[i];
    v.x = rtf(v.x); v.y = rtf(v.y); v.z = rtf(v.z); v.w = rtf(v.w);
    dst[i] = v;
}

// rel rounding into both g_relr and the K-padded g_relp (same layout)
__global__ void round_rel_kernel(const float4* __restrict__ src) {
    int i = blockIdx.x * blockDim.x + threadIdx.x;
    int n4 = (65 * DP_) / 4;
    if (i >= n4) return;
    float4 v = src[i];
    v.x = rtf(v.x); v.y = rtf(v.y); v.z = rtf(v.z); v.w = rtf(v.w);
    ((float4*)g_relr)[i] = v;
    ((float4*)g_relp)[i] = v;
}

// batched variant: y selects one of 4 (src,dst) pairs (all same n4)
__global__ void round4_kernel(const float4* s0, float4* d0,
                              const float4* s1, float4* d1,
                              const float4* s2, float4* d2,
                              const float4* s3, float4* d3, int n4) {
    int i = blockIdx.x * blockDim.x + threadIdx.x;
    if (i >= n4) return;
    const float4* s; float4* d;
    switch (blockIdx.y) {
        case 0: s = s0; d = d0; break;
        case 1: s = s1; d = d1; break;
        case 2: s = s2; d = d2; break;
        default: s = s3; d = d3; break;
    }
    float4 v = s[i];
    v.x = rtf(v.x); v.y = rtf(v.y); v.z = rtf(v.z); v.w = rtf(v.w);
    d[i] = v;
}

// ---------------------------------------------------------------------------
// 0) Mask normalization + row compaction (single block)
// ---------------------------------------------------------------------------
__global__ void mask_norm_kernel(const void* raw) {
    __shared__ int f_int, f_flt;
    const unsigned int* w = (const unsigned int*)raw;
    int t = threadIdx.x;  // 1024 threads
    if (t == 0) { f_int = 1; f_flt = 1; g_nrows = 0; }
    __syncthreads();
    unsigned int x = w[t];
    if (x != 0u && x != 1u) f_int = 0;
    if (x != 0u && x != 0x3F800000u) f_flt = 0;
    __syncthreads();
    if (f_int) {
        for (int i = t; i < MS_; i += 1024) g_mask[i] = (int)w[i];
    } else if (f_flt) {
        const float* f = (const float*)raw;
        for (int i = t; i < MS_; i += 1024) g_mask[i] = (f[i] != 0.f);
    } else {
        const unsigned char* bts = (const unsigned char*)raw;
        for (int i = t; i < MS_; i += 1024) g_mask[i] = (bts[i] != 0);
    }
    __syncthreads();
    for (int i = t; i < MS_; i += 1024) {
        if (!g_mask[i]) {
            int pos = atomicAdd(&g_nrows, 1);
            g_rowidx[pos] = i;
        }
    }
}

// ---------------------------------------------------------------------------
// 0b) Zero-fill q/k/v for masked rows (their GEMM result is skipped)
// ---------------------------------------------------------------------------
__global__ void zero_masked_kernel() {
    int i = blockIdx.x * 256 + threadIdx.x;
    if (i >= MS_ * D_) return;
    int m = i >> 10;
    if (!g_mask[m]) return;
    int n = i & 1023;
    int b = m >> 9, s = m & 511;
    int h = n >> 7, d = n & 127;
    size_t off = ((size_t)((b * H_ + h) * S_ + s)) * DP_ + d;
    g_q[off] = 0.f; g_k[off] = 0.f; g_v[off] = 0.f;
}

// ---------------------------------------------------------------------------
// 1) QKV projections on COMPACTED rows + bias + head-major scatter
// ---------------------------------------------------------------------------
__global__ void __launch_bounds__(256) qkv_kernel(
    const float* __restrict__ bq, const float* __restrict__ bk,
    const float* __restrict__ bv) {
    const int nrows = g_nrows;
    const int bm = blockIdx.y * 128;
    if (bm >= nrows) return;
    const int z = blockIdx.z;
    const float* W    = (z == 0) ? g_Wqr : (z == 1) ? g_Wkr : g_Wvr;
    const float* bias = (z == 0) ? bq : (z == 1) ? bk : bv;
    float* out        = (z == 0) ? g_q : (z == 1) ? g_k : g_v;
    const int bn = blockIdx.x * 128;
    ca_tn(D_,
        [&](int r, int k) {
            int idx = bm + r;
            int m = g_rowidx[idx < nrows ? idx : 0];
            return g_xr + (size_t)m * D_ + k;
        },
        [&](int r, int k) { return W + (size_t)(bn + r) * D_ + k; },
        [&](int il, int jl, float v) {
            int idx = bm + il;
            if (idx >= nrows) return;
            int m = g_rowidx[idx], n = bn + jl;
            int b = m >> 9, s = m & 511;
            int h = n >> 7, d = n & 127;
            out[((size_t)((b * H_ + h) * S_ + s)) * DP_ + d] = rtf(v + bias[n]);
        });
}

// ---------------------------------------------------------------------------
// 2) RNN input GEMMs
// ---------------------------------------------------------------------------
__device__ __forceinline__ const float* feats_row(int rr) {
    int f = rr >> 14;
    int rem = rr & 16383;
    int bh4 = rem >> 9;
    int s   = rem & 511;
    int b = bh4 >> 2, hh = bh4 & 3;
    const float* src = (f == 0) ? g_q : (f == 1) ? g_k : g_v;
    return src + ((size_t)((b * H_ + 4 + hh) * S_ + s)) * DP_;
}

__global__ void __launch_bounds__(256) rnn_in_kernel(
    const float* __restrict__ bih_f, const float* __restrict__ bih_b) {
    const int z = blockIdx.z;
    const float* W    = z ? g_Wihbr : g_Wihfr;
    const float* bias = z ? bih_b : bih_f;
    float* dst        = z ? g_Bm : g_A;
    const int bm = blockIdx.y * 128;
    ca_tn(DP_,
        [&](int r, int k) { return feats_row(bm + r) + k; },
        [&](int r, int k) { return W + (size_t)r * DP_ + k; },
        [&](int il, int jl, float v) {
            dst[(size_t)(bm + il) * DP_ + jl] = v + bias[jl];
        });
}

// ---------------------------------------------------------------------------
// 3) First RNN step (elementwise; rounded out -- H1 feeds GEMMs)
// ---------------------------------------------------------------------------
__global__ void rnn_h1_kernel(const float* __restrict__ bih_f,
                              const float* __restrict__ bhh_f,
                              const float* __restrict__ bhh_b) {
    int gid = blockIdx.x * blockDim.x + threadIdx.x;
    if (gid >= NR_ * DP_) return;
    int r = gid >> 7, d = gid & 127;
    int s = r & 511;
    float af = s ? g_A[gid - DP_] : bih_f[d];
    g_H1f[gid] = rtf(tanhf(af + bhh_f[d]));
    g_H1b[gid] = rtf(tanhf(g_Bm[gid] + bhh_b[d]));
}

// ---------------------------------------------------------------------------
// 4) Forward step 2:  Yf = tanh( A + H1f@Whh_f^T + bhh_f )
// ---------------------------------------------------------------------------
__global__ void __launch_bounds__(256) rnn_h2f_kernel(const float* __restrict__ bhh_f) {
    const int bm = blockIdx.y * 128;
    ca_tn(DP_,
        [&](int r, int k) { return g_H1f + (size_t)(bm + r) * DP_ + k; },
        [&](int r, int k) { return g_Whhfr + (size_t)r * DP_ + k; },
        [&](int il, int jl, float v) {
            size_t idx = (size_t)(bm + il) * DP_ + jl;
            g_Yf[idx] = tanhf(v + g_A[idx] + bhh_f[jl]);
        });
}

// ---------------------------------------------------------------------------
// 5) Backward step 2 + combine + scatter back into q/k/v heads 4..7 (rounded)
// ---------------------------------------------------------------------------
__global__ void __launch_bounds__(256) rnn_h2b_kernel(
    const float* __restrict__ bih_b, const float* __restrict__ bhh_b) {
    const int bm = blockIdx.y * 128;
    ca_tn(DP_,
        [&](int r, int k) { return g_H1b + (size_t)(bm + r) * DP_ + k; },
        [&](int r, int k) { return g_Whhbr + (size_t)r * DP_ + k; },
        [&](int il, int jl, float v) {
            int m = bm + il, n = jl;
            int s = m & 511;
            float shiftB = s ? g_Bm[(size_t)(m - 1) * DP_ + n] : bih_b[n];
            float y = g_Yf[(size_t)m * DP_ + n] + tanhf(v + shiftB + bhh_b[n]);
            int f = m >> 14, rem = m & 16383, bh4 = rem >> 9;
            int b = bh4 >> 2, hh = bh4 & 3;
            float* dst = (f == 0) ? g_q : (f == 1) ? g_k : g_v;
            dst[((size_t)((b * H_ + 4 + hh) * S_ + s)) * DP_ + n] = rtf(y);
        });
}

// ---------------------------------------------------------------------------
// 6) P = (q . rel_emb^T)/SCALE as tf32 GEMM (M=32768, N=65 padded to 128)
// ---------------------------------------------------------------------------
__global__ void __launch_bounds__(256) p_gemm_kernel() {
    const int bm = blockIdx.y * 128;
    ca_tn(DP_,
        [&](int r, int k) { return g_q + (size_t)(bm + r) * DP_ + k; },
        [&](int r, int k) { return g_relr + (size_t)(r < 65 ? r : 64) * DP_ + k; },
        [&](int il, int jl, float v) {
            if (jl < 65) g_P[(size_t)(bm + il) * 65 + jl] = v * INV_SCALE;
        });
}

// ---------------------------------------------------------------------------
// 7) scores (pre-softmax) into the attn buffer
// ---------------------------------------------------------------------------
__global__ void __launch_bounds__(256) scores_kernel(float* __restrict__ attn,
                                                     int attn_in_out) {
    float* ap = attn_in_out ? attn : g_attn_fb;
    const int z = blockIdx.z;
    const int b = z >> 3;
    const int bm = blockIdx.y * 128, bn = blockIdx.x * 128;
    const float* qb = g_q + (size_t)z * S_ * DP_;
    const float* kb = g_k + (size_t)z * S_ * DP_;
    ca_tn(DP_,
        [&](int r, int k) { return qb + (size_t)(bm + r) * DP_ + k; },
        [&](int r, int k) { return kb + (size_t)(bn + r) * DP_ + k; },
        [&](int il, int jl, float v) {
            int qi = bm + il, ki = bn + jl;
            float val;
            if (g_mask[b * S_ + ki]) {
                val = -1e18f;
            } else {
                int off = ki - qi;
                off = off < -32 ? -32 : (off > 32 ? 32 : off);
                val = v * INV_SCALE + g_P[((size_t)z * S_ + qi) * 65 + off + 32];
            }
            ap[(size_t)z * S_ * S_ + (size_t)qi * S_ + ki] = val;
        });
}

// ---------------------------------------------------------------------------
// 8) Softmax per row + bucketed rel sums R (stride 80)
// ---------------------------------------------------------------------------
__device__ __forceinline__ float blk_reduce(float v, float* red, bool is_max) {
#pragma unroll
    for (int o = 16; o > 0; o >>= 1) {
        float w = __shfl_xor_sync(0xffffffffu, v, o);
        v = is_max ? fmaxf(v, w) : (v + w);
    }
    int warp = threadIdx.x >> 5, lane = threadIdx.x & 31;
    if (lane == 0) red[warp] = v;
    __syncthreads();
    float r = red[0];
#pragma unroll
    for (int i = 1; i < 8; i++) r = is_max ? fmaxf(r, red[i]) : (r + red[i]);
    __syncthreads();
    return r;
}

__global__ void __launch_bounds__(256) softmax_kernel(float* __restrict__ attn,
                                                      int attn_in_out) {
    float* ap = attn_in_out ? attn : g_attn_fb;
    int row = blockIdx.x;
    int q = row & 511;
    float* p = ap + (size_t)row * S_;
    __shared__ float sh[S_];
    __shared__ float red[8];
    int t = threadIdx.x;
    float v0 = p[t], v1 = p[t + 256];
    float mx = blk_reduce(fmaxf(v0, v1), red, true);
    float e0 = expf(v0 - mx), e1 = expf(v1 - mx);
    float sum = blk_reduce(e0 + e1, red, false);
    float inv = 1.f / sum;
    e0 *= inv; e1 *= inv;
    p[t] = e0; p[t + 256] = e1;
    sh[t] = e0; sh[t + 256] = e1;
    float r0 = 0.f, r64 = 0.f;
    if (t <= q - 32)        r0  += e0;
    if (t >= q + 32)        r64 += e0;
    if (t + 256 <= q - 32)  r0  += e1;
    if (t + 256 >= q + 32)  r64 += e1;
    r0  = blk_reduce(r0,  red, false);
    r64 = blk_reduce(r64, red, false);
    float* Rr = g_R + (size_t)row * RK_;
    if (t == 0) { Rr[0] = r0; Rr[64] = r64; }
    if (t >= 1 && t <= 63) {
        int k = q + t - 32;
        Rr[t] = (k >= 0 && k < S_) ? sh[k] : 0.f;
    }
}

// ---------------------------------------------------------------------------
// 9) ctx = attn @ v  (NN, per bh)
// ---------------------------------------------------------------------------
__global__ void __launch_bounds__(256) ctx_kernel(const float* __restrict__ attn,
                                                  int attn_in_out) {
    const float* ap = attn_in_out ? attn : g_attn_fb;
    const int z = blockIdx.z;
    const int bm = blockIdx.y * 128;
    const float* Ab = ap + (size_t)z * S_ * S_;
    const float* Vb = g_v + (size_t)z * S_ * DP_;
    ca_nn(S_,
        [&](int r, int k) { return Ab + (size_t)(bm + r) * S_ + k; },
        [&](int k, int n) { return Vb + (size_t)k * DP_ + n; },
        [&](int il, int jl, float v) {
            g_ctx[(size_t)z * S_ * DP_ + (size_t)(bm + il) * DP_ + jl] = v;
        });
}

// ---------------------------------------------------------------------------
// 10) ctx += R @ rel_emb as tf32 GEMM (M=32768, N=128, K=80 padded)
// ---------------------------------------------------------------------------
__global__ void __launch_bounds__(256) ctx_rel_gemm_kernel() {
    const int bm = blockIdx.y * 128;
    ca_nn(RK_,
        [&](int r, int k) { return g_R + (size_t)(bm + r) * RK_ + k; },
        [&](int k, int n) { return g_relp + (size_t)k * DP_ + n; },
        [&](int il, int jl, float v) {
            size_t idx = (size_t)(bm + il) * DP_ + jl;
            g_ctx[idx] = rtf(g_ctx[idx] + v);
        });
}

// ---------------------------------------------------------------------------
// 11) out = ctx_perm @ Wo^T + bo
// ---------------------------------------------------------------------------
__global__ void __launch_bounds__(256) out_kernel(const float* __restrict__ bo,
                                                  float* __restrict__ out) {
    const int bm = blockIdx.y * 128, bn = blockIdx.x * 128;
    ca_tn(D_,
        [&](int r, int k) {
            int m = bm + r;
            int b = m >> 9, s = m & 511;
            int h = k >> 7, d = k & 127;
            return g_ctx + ((size_t)((b * H_ + h) * S_ + s)) * DP_ + d;
        },
        [&](int r, int k) { return g_Wor + (size_t)(bn + r) * D_ + k; },
        [&](int il, int jl, float v) {
            int m = bm + il, n = bn + jl;
            out[(size_t)m * D_ + n] = v + bo[n];
        });
}

// ---------------------------------------------------------------------------
// Host launcher
// ---------------------------------------------------------------------------
extern "C" void kernel_launch(void* const* d_in, const int* in_sizes, int n_in,
                              void* d_out, int out_size) {
    const float* x     = (const float*)d_in[0];
    const void*  mask  = d_in[1];
    const float* Wq    = (const float*)d_in[2];
    const float* bq    = (const float*)d_in[3];
    const float* Wk    = (const float*)d_in[4];
    const float* bk    = (const float*)d_in[5];
    const float* Wv    = (const float*)d_in[6];
    const float* bv    = (const float*)d_in[7];
    const float* Wo    = (const float*)d_in[8];
    const float* bo    = (const float*)d_in[9];
    const float* rel   = (const float*)d_in[10];
    const float* Wih_f = (const float*)d_in[11];
    const float* Whh_f = (const float*)d_in[12];
    const float* bih_f = (const float*)d_in[13];
    const float* bhh_f = (const float*)d_in[14];
    const float* Wih_b = (const float*)d_in[15];
    const float* Whh_b = (const float*)d_in[16];
    const float* bih_b = (const float*)d_in[17];
    const float* bhh_b = (const float*)d_in[18];

    float* out = (float*)d_out;
    const int attn_in_out = (out_size >= NOUT_ + BH_ * S_ * S_) ? 1 : 0;
    float* attn = attn_in_out ? (out + NOUT_) : nullptr;

    static int smem_set = 0;
    if (!smem_set) {
        cudaFuncSetAttribute(qkv_kernel,         cudaFuncAttributeMaxDynamicSharedMemorySize, SMEM_TN);
        cudaFuncSetAttribute(rnn_in_kernel,      cudaFuncAttributeMaxDynamicSharedMemorySize, SMEM_TN);
        cudaFuncSetAttribute(rnn_h2f_kernel,     cudaFuncAttributeMaxDynamicSharedMemorySize, SMEM_TN);
        cudaFuncSetAttribute(rnn_h2b_kernel,     cudaFuncAttributeMaxDynamicSharedMemorySize, SMEM_TN);
        cudaFuncSetAttribute(p_gemm_kernel,      cudaFuncAttributeMaxDynamicSharedMemorySize, SMEM_TN);
        cudaFuncSetAttribute(scores_kernel,      cudaFuncAttributeMaxDynamicSharedMemorySize, SMEM_TN);
        cudaFuncSetAttribute(ctx_kernel,         cudaFuncAttributeMaxDynamicSharedMemorySize, SMEM_NN);
        cudaFuncSetAttribute(ctx_rel_gemm_kernel,cudaFuncAttributeMaxDynamicSharedMemorySize, SMEM_NN);
        cudaFuncSetAttribute(out_kernel,         cudaFuncAttributeMaxDynamicSharedMemorySize, SMEM_TN);
        smem_set = 1;
    }

    // device pointers to rounded-copy buffers
    float* p_xr;  cudaGetSymbolAddress((void**)&p_xr,  g_xr);
    float* p_wq;  cudaGetSymbolAddress((void**)&p_wq,  g_Wqr);
    float* p_wk;  cudaGetSymbolAddress((void**)&p_wk,  g_Wkr);
    float* p_wv;  cudaGetSymbolAddress((void**)&p_wv,  g_Wvr);
    float* p_wo;  cudaGetSymbolAddress((void**)&p_wo,  g_Wor);
    float* p_wif; cudaGetSymbolAddress((void**)&p_wif, g_Wihfr);
    float* p_whf; cudaGetSymbolAddress((void**)&p_whf, g_Whhfr);
    float* p_wib; cudaGetSymbolAddress((void**)&p_wib, g_Wihbr);
    float* p_whb; cudaGetSymbolAddress((void**)&p_whb, g_Whhbr);

    // tf32 pre-rounding (rna): x, big weights (batched), rnn weights (batched), rel
    {
        int n4 = (MS_ * D_) / 4;
        round_kernel<<<(n4 + 255) / 256, 256>>>((const float4*)x, (float4*)p_xr, n4);
    }
    {
        int n4 = (D_ * D_) / 4;
        round4_kernel<<<dim3((n4 + 255) / 256, 4), 256>>>(
            (const float4*)Wq, (float4*)p_wq, (const float4*)Wk, (float4*)p_wk,
            (const float4*)Wv, (float4*)p_wv, (const float4*)Wo, (float4*)p_wo, n4);
    }
    {
        int n4 = (DP_ * DP_) / 4;
        round4_kernel<<<dim3((n4 + 255) / 256, 4), 256>>>(
            (const float4*)Wih_f, (float4*)p_wif, (const float4*)Whh_f, (float4*)p_whf,
            (const float4*)Wih_b, (float4*)p_wib, (const float4*)Whh_b, (float4*)p_whb, n4);
    }
    {
        int n4 = (65 * DP_) / 4;
        round_rel_kernel<<<(n4 + 255) / 256, 256>>>((const float4*)rel);
    }

    mask_norm_kernel<<<1, 1024>>>(mask);

    // zero-fill masked rows, then compute only unmasked rows
    zero_masked_kernel<<<(MS_ * D_ + 255) / 256, 256>>>();
    qkv_kernel<<<dim3(D_ / 128, MS_ / 128, 3), 256, SMEM_TN>>>(bq, bk, bv);

    rnn_in_kernel<<<dim3(1, NR_ / 128, 2), 256, SMEM_TN>>>(bih_f, bih_b);
    rnn_h1_kernel<<<(NR_ * DP_) / 256, 256>>>(bih_f, bhh_f, bhh_b);
    rnn_h2f_kernel<<<dim3(1, NR_ / 128), 256, SMEM_TN>>>(bhh_f);
    rnn_h2b_kernel<<<dim3(1, NR_ / 128), 256, SMEM_TN>>>(bih_b, bhh_b);

    p_gemm_kernel<<<dim3(1, ROWS_ / 128), 256, SMEM_TN>>>();

    scores_kernel<<<dim3(S_ / 128, S_ / 128, BH_), 256, SMEM_TN>>>(attn, attn_in_out);
    softmax_kernel<<<ROWS_, 256>>>(attn, attn_in_out);
    ctx_kernel<<<dim3(1, S_ / 128, BH_), 256, SMEM_NN>>>(attn, attn_in_out);
    ctx_rel_gemm_kernel<<<dim3(1, ROWS_ / 128), 256, SMEM_NN>>>();
    out_kernel<<<dim3(D_ / 128, MS_ / 128), 256, SMEM_TN>>>(bo, out);
}

// round 17
// speedup vs baseline: 2.8386x; 1.0210x over previous
#include <cuda_runtime.h>
#include <cstdint>
#include <math.h>

// ---------------------------------------------------------------------------
// Problem constants
// ---------------------------------------------------------------------------
namespace {
constexpr int B_   = 8;
constexpr int S_   = 512;
constexpr int D_   = 1024;
constexpr int H_   = 8;
constexpr int DP_  = 128;              // head dim
constexpr int BH_  = B_ * H_;          // 64
constexpr int MS_  = B_ * S_;          // 4096  (rows of x)
constexpr int NR_  = 96 * S_;          // 49152 RNN rows
constexpr int ROWS_ = BH_ * S_;        // 32768 (b,h,q) rows
constexpr int NOUT_ = MS_ * D_;        // 4194304 elements of `out`
constexpr float INV_SCALE = 0.08838834764831845f;  // 1/sqrt(128)
constexpr int RK_  = 80;               // padded K for the R@rel GEMM
// smem: A[3][128][20] + B_tn[3][128][20]  /  B_nn[3][16][136]
constexpr int SMEM_TN = (3 * 128 * 20 + 3 * 128 * 20) * 4;   // 61440
constexpr int SMEM_NN = (3 * 128 * 20 + 3 * 16 * 136) * 4;   // 56832
}

// ---------------------------------------------------------------------------
// Scratch (static device globals -- no runtime allocation allowed)
// ---------------------------------------------------------------------------
__device__ float g_q  [BH_ * S_ * DP_];
__device__ float g_k  [BH_ * S_ * DP_];
__device__ float g_v  [BH_ * S_ * DP_];
__device__ float g_kc [BH_ * S_ * DP_];   // key-compacted k
__device__ float g_vc [BH_ * S_ * DP_];   // key-compacted v
__device__ float g_ctx[BH_ * S_ * DP_];
__device__ float g_A  [NR_ * DP_];
__device__ float g_Bm [NR_ * DP_];
__device__ float g_H1f[NR_ * DP_];
__device__ float g_H1b[NR_ * DP_];
__device__ float g_Yf [NR_ * DP_];
__device__ float g_P  [ROWS_ * 65];
__device__ float g_R  [ROWS_ * RK_];   // stride 80; cols 65..79 stay zero
__device__ int   g_mask[MS_];
__device__ int   g_rowidx[MS_];        // compacted unmasked row indices (qkv)
__device__ int   g_nrows;              // number of unmasked rows
__device__ int   g_kidx[MS_];          // per-batch ordered unmasked key list
__device__ int   g_kpos[MS_];          // inverse map: key -> compact position
__device__ int   g_nk[B_];             // per-batch unmasked key count
__device__ float g_attnc[(size_t)BH_ * S_ * S_];  // compacted scores/attn
__device__ float g_attn_fb[(size_t)BH_ * S_ * S_];
// tf32-rounded operand copies
__device__ float g_xr  [MS_ * D_];
__device__ float g_Wqr [D_ * D_];
__device__ float g_Wkr [D_ * D_];
__device__ float g_Wvr [D_ * D_];
__device__ float g_Wor [D_ * D_];
__device__ float g_Wihfr[DP_ * DP_];
__device__ float g_Whhfr[DP_ * DP_];
__device__ float g_Wihbr[DP_ * DP_];
__device__ float g_Whhbr[DP_ * DP_];
__device__ float g_relr [65 * DP_];    // rounded rel (for P gemm, row-gather)
__device__ float g_relp [RK_ * DP_];   // rounded rel, K-padded (rows 65..79 zero)

// ---------------------------------------------------------------------------
// tf32 / cp.async helpers
// ---------------------------------------------------------------------------
__device__ __forceinline__ unsigned f2tf(float x) {
    unsigned r;
    asm("cvt.rna.tf32.f32 %0, %1;" : "=r"(r) : "f"(x));
    return r;
}
__device__ __forceinline__ float rtf(float x) { return __uint_as_float(f2tf(x)); }

__device__ __forceinline__ void mma_tf32(float* d, const unsigned* a, const unsigned* b) {
    asm volatile(
        "mma.sync.aligned.m16n8k8.row.col.f32.tf32.tf32.f32 "
        "{%0,%1,%2,%3}, {%4,%5,%6,%7}, {%8,%9}, {%0,%1,%2,%3};\n"
        : "+f"(d[0]), "+f"(d[1]), "+f"(d[2]), "+f"(d[3])
        : "r"(a[0]), "r"(a[1]), "r"(a[2]), "r"(a[3]), "r"(b[0]), "r"(b[1]));
}

__device__ __forceinline__ void cp16(void* s, const void* g) {
    unsigned a = (unsigned)__cvta_generic_to_shared(s);
    asm volatile("cp.async.cg.shared.global [%0], [%1], 16;" :: "r"(a), "l"(g));
}
__device__ __forceinline__ void cp_commit() { asm volatile("cp.async.commit_group;"); }
__device__ __forceinline__ void cp_wait1()  { asm volatile("cp.async.wait_group 1;"); }

// ---------------------------------------------------------------------------
// 128x128 tf32 MMA cores with cp.async 3-stage pipeline (R7 proven core).
// 256 threads = 8 warps (2M x 4N), warp tile 64x32.
// ---------------------------------------------------------------------------
template <class FA, class FB, class FC>
__device__ __forceinline__ void ca_tn(int K, FA rowA, FB rowB, FC storeC) {
    extern __shared__ unsigned sm_[];
    unsigned (*As)[128][20] = reinterpret_cast<unsigned(*)[128][20]>(sm_);
    unsigned (*Bs)[128][20] = reinterpret_cast<unsigned(*)[128][20]>(sm_ + 3 * 128 * 20);
    const int tid  = threadIdx.x;
    const int lane = tid & 31, warp = tid >> 5;
    const int la3  = lane & 3, lg = lane >> 2;
    const int wm   = (warp & 1) * 64, wn = (warp >> 1) * 32;
    const int lr   = tid >> 2, lc = (tid & 3) * 4;
    float acc[4][4][4] = {};
    const int nk = K / 16;
    auto issue = [&](int st, int k0) {
        cp16(&As[st][lr][lc],      rowA(lr,      k0 + lc));
        cp16(&As[st][lr + 64][lc], rowA(lr + 64, k0 + lc));
        cp16(&Bs[st][lr][lc],      rowB(lr,      k0 + lc));
        cp16(&Bs[st][lr + 64][lc], rowB(lr + 64, k0 + lc));
    };
    issue(0, 0);  cp_commit();
    issue(1, 16); cp_commit();
    int st = 0;
    for (int it = 0; it < nk; it++) {
        cp_wait1();
        __syncthreads();
        if (it + 2 < nk) {
            int ns = st + 2; if (ns >= 3) ns -= 3;
            issue(ns, (it + 2) * 16);
        }
        cp_commit();
#pragma unroll
        for (int kc = 0; kc < 16; kc += 8) {
            unsigned af[4][4], bf[4][2];
#pragma unroll
            for (int mi = 0; mi < 4; mi++) {
                int m0 = wm + 16 * mi;
                af[mi][0] = As[st][m0 + lg][kc + la3];
                af[mi][1] = As[st][m0 + 8 + lg][kc + la3];
                af[mi][2] = As[st][m0 + lg][kc + 4 + la3];
                af[mi][3] = As[st][m0 + 8 + lg][kc + 4 + la3];
            }
#pragma unroll
            for (int nj = 0; nj < 4; nj++) {
                int n0 = wn + 8 * nj;
                bf[nj][0] = Bs[st][n0 + lg][kc + la3];
                bf[nj][1] = Bs[st][n0 + lg][kc + 4 + la3];
            }
#pragma unroll
            for (int mi = 0; mi < 4; mi++)
#pragma unroll
                for (int nj = 0; nj < 4; nj++) mma_tf32(acc[mi][nj], af[mi], bf[nj]);
        }
        if (++st == 3) st = 0;
    }
#pragma unroll
    for (int mi = 0; mi < 4; mi++)
#pragma unroll
        for (int nj = 0; nj < 4; nj++) {
            int r = wm + 16 * mi + lg, c = wn + 8 * nj + 2 * la3;
            storeC(r,     c,     acc[mi][nj][0]);
            storeC(r,     c + 1, acc[mi][nj][1]);
            storeC(r + 8, c,     acc[mi][nj][2]);
            storeC(r + 8, c + 1, acc[mi][nj][3]);
        }
}

template <class FA, class FB, class FC>
__device__ __forceinline__ void ca_nn(int K, FA rowA, FB rowB, FC storeC) {
    extern __shared__ unsigned sm_[];
    unsigned (*As)[128][20] = reinterpret_cast<unsigned(*)[128][20]>(sm_);
    unsigned (*Bs)[16][136] = reinterpret_cast<unsigned(*)[16][136]>(sm_ + 3 * 128 * 20);
    const int tid  = threadIdx.x;
    const int lane = tid & 31, warp = tid >> 5;
    const int la3  = lane & 3, lg = lane >> 2;
    const int wm   = (warp & 1) * 64, wn = (warp >> 1) * 32;
    const int lr   = tid >> 2, lc = (tid & 3) * 4;
    const int br   = tid >> 5, bc = (tid & 31) * 4;
    float acc[4][4][4] = {};
    const int nk = K / 16;
    auto issue = [&](int st, int k0) {
        cp16(&As[st][lr][lc],      rowA(lr,      k0 + lc));
        cp16(&As[st][lr + 64][lc], rowA(lr + 64, k0 + lc));
        cp16(&Bs[st][br][bc],      rowB(k0 + br,     bc));
        cp16(&Bs[st][br + 8][bc],  rowB(k0 + br + 8, bc));
    };
    issue(0, 0);  cp_commit();
    issue(1, 16); cp_commit();
    int st = 0;
    for (int it = 0; it < nk; it++) {
        cp_wait1();
        __syncthreads();
        if (it + 2 < nk) {
            int ns = st + 2; if (ns >= 3) ns -= 3;
            issue(ns, (it + 2) * 16);
        }
        cp_commit();
#pragma unroll
        for (int kc = 0; kc < 16; kc += 8) {
            unsigned af[4][4], bf[4][2];
#pragma unroll
            for (int mi = 0; mi < 4; mi++) {
                int m0 = wm + 16 * mi;
                af[mi][0] = As[st][m0 + lg][kc + la3];
                af[mi][1] = As[st][m0 + 8 + lg][kc + la3];
                af[mi][2] = As[st][m0 + lg][kc + 4 + la3];
                af[mi][3] = As[st][m0 + 8 + lg][kc + 4 + la3];
            }
#pragma unroll
            for (int nj = 0; nj < 4; nj++) {
                int n0 = wn + 8 * nj;
                bf[nj][0] = Bs[st][kc + la3][n0 + lg];
                bf[nj][1] = Bs[st][kc + 4 + la3][n0 + lg];
            }
#pragma unroll
            for (int mi = 0; mi < 4; mi++)
#pragma unroll
                for (int nj = 0; nj < 4; nj++) mma_tf32(acc[mi][nj], af[mi], bf[nj]);
        }
        if (++st == 3) st = 0;
    }
#pragma unroll
    for (int mi = 0; mi < 4; mi++)
#pragma unroll
        for (int nj = 0; nj < 4; nj++) {
            int r = wm + 16 * mi + lg, c = wn + 8 * nj + 2 * la3;
            storeC(r,     c,     acc[mi][nj][0]);
            storeC(r,     c + 1, acc[mi][nj][1]);
            storeC(r + 8, c,     acc[mi][nj][2]);
            storeC(r + 8, c + 1, acc[mi][nj][3]);
        }
}

// ---------------------------------------------------------------------------
// tf32 pre-rounding of GEMM operands (rna, once)
// ---------------------------------------------------------------------------
__global__ void round_kernel(const float4* __restrict__ src, float4* __restrict__ dst, int n4) {
    int i = blockIdx.x * blockDim.x + threadIdx.x;
    if (i >= n4) return;
    float4 v = src[i];
    v.x = rtf(v.x); v.y = rtf(v.y); v.z = rtf(v.z); v.w = rtf(v.w);
    dst[i] = v;
}

__global__ void round_rel_kernel(const float4* __restrict__ src) {
    int i = blockIdx.x * blockDim.x + threadIdx.x;
    int n4 = (65 * DP_) / 4;
    if (i >= n4) return;
    float4 v = src[i];
    v.x = rtf(v.x); v.y = rtf(v.y); v.z = rtf(v.z); v.w = rtf(v.w);
    ((float4*)g_relr)[i] = v;
    ((float4*)g_relp)[i] = v;
}

__global__ void round4_kernel(const float4* s0, float4* d0,
                              const float4* s1, float4* d1,
                              const float4* s2, float4* d2,
                              const float4* s3, float4* d3, int n4) {
    int i = blockIdx.x * blockDim.x + threadIdx.x;
    if (i >= n4) return;
    const float4* s; float4* d;
    switch (blockIdx.y) {
        case 0: s = s0; d = d0; break;
        case 1: s = s1; d = d1; break;
        case 2: s = s2; d = d2; break;
        default: s = s3; d = d3; break;
    }
    float4 v = s[i];
    v.x = rtf(v.x); v.y = rtf(v.y); v.z = rtf(v.z); v.w = rtf(v.w);
    d[i] = v;
}

// ---------------------------------------------------------------------------
// 0) Mask normalization + row compaction + per-batch key compaction
// ---------------------------------------------------------------------------
__global__ void mask_norm_kernel(const void* raw) {
    __shared__ int f_int, f_flt;
    const unsigned int* w = (const unsigned int*)raw;
    int t = threadIdx.x;  // 1024 threads
    if (t == 0) { f_int = 1; f_flt = 1; g_nrows = 0; }
    __syncthreads();
    unsigned int x = w[t];
    if (x != 0u && x != 1u) f_int = 0;
    if (x != 0u && x != 0x3F800000u) f_flt = 0;
    __syncthreads();
    if (f_int) {
        for (int i = t; i < MS_; i += 1024) g_mask[i] = (int)w[i];
    } else if (f_flt) {
        const float* f = (const float*)raw;
        for (int i = t; i < MS_; i += 1024) g_mask[i] = (f[i] != 0.f);
    } else {
        const unsigned char* bts = (const unsigned char*)raw;
        for (int i = t; i < MS_; i += 1024) g_mask[i] = (bts[i] != 0);
    }
    __syncthreads();
    // row compaction (order-free; consumers are per-row independent)
    for (int i = t; i < MS_; i += 1024) {
        if (!g_mask[i]) {
            int pos = atomicAdd(&g_nrows, 1);
            g_rowidx[pos] = i;
        }
    }
    // per-batch ordered key compaction (deterministic sequential scan)
    if (t < B_) {
        int cnt = 0;
        for (int k = 0; k < S_; k++) {
            if (!g_mask[t * S_ + k]) {
                g_kidx[t * S_ + cnt] = k;
                g_kpos[t * S_ + k] = cnt;
                cnt++;
            }
        }
        g_nk[t] = cnt;
    }
}

// ---------------------------------------------------------------------------
// 0b) Zero-fill q/k/v for masked rows (their GEMM result is skipped)
// ---------------------------------------------------------------------------
__global__ void zero_masked_kernel() {
    int i = blockIdx.x * 256 + threadIdx.x;
    if (i >= MS_ * D_) return;
    int m = i >> 10;
    if (!g_mask[m]) return;
    int n = i & 1023;
    int b = m >> 9, s = m & 511;
    int h = n >> 7, d = n & 127;
    size_t off = ((size_t)((b * H_ + h) * S_ + s)) * DP_ + d;
    g_q[off] = 0.f; g_k[off] = 0.f; g_v[off] = 0.f;
}

// ---------------------------------------------------------------------------
// 0c) Gather compacted k/v (after RNN updates). One thread per float4 chunk.
// ---------------------------------------------------------------------------
__global__ void gather_kv_kernel() {
    int i = blockIdx.x * 256 + threadIdx.x;      // over BH_*S_*32 float4s
    if (i >= BH_ * S_ * 32) return;
    int c = i & 31;
    int rj = i >> 5;
    int z = rj >> 9, j = rj & 511;
    int b = z >> 3;
    if (j >= g_nk[b]) return;
    int ks = g_kidx[b * S_ + j];
    size_t dst = ((size_t)z * S_ + j) * 32 + c;
    size_t src = ((size_t)z * S_ + ks) * 32 + c;
    ((float4*)g_kc)[dst] = ((const float4*)g_k)[src];
    ((float4*)g_vc)[dst] = ((const float4*)g_v)[src];
}

// ---------------------------------------------------------------------------
// 1) QKV projections on COMPACTED rows + bias + head-major scatter
// ---------------------------------------------------------------------------
__global__ void __launch_bounds__(256) qkv_kernel(
    const float* __restrict__ bq, const float* __restrict__ bk,
    const float* __restrict__ bv) {
    const int nrows = g_nrows;
    const int bm = blockIdx.y * 128;
    if (bm >= nrows) return;
    const int z = blockIdx.z;
    const float* W    = (z == 0) ? g_Wqr : (z == 1) ? g_Wkr : g_Wvr;
    const float* bias = (z == 0) ? bq : (z == 1) ? bk : bv;
    float* out        = (z == 0) ? g_q : (z == 1) ? g_k : g_v;
    const int bn = blockIdx.x * 128;
    ca_tn(D_,
        [&](int r, int k) {
            int idx = bm + r;
            int m = g_rowidx[idx < nrows ? idx : 0];
            return g_xr + (size_t)m * D_ + k;
        },
        [&](int r, int k) { return W + (size_t)(bn + r) * D_ + k; },
        [&](int il, int jl, float v) {
            int idx = bm + il;
            if (idx >= nrows) return;
            int m = g_rowidx[idx], n = bn + jl;
            int b = m >> 9, s = m & 511;
            int h = n >> 7, d = n & 127;
            out[((size_t)((b * H_ + h) * S_ + s)) * DP_ + d] = rtf(v + bias[n]);
        });
}

// ---------------------------------------------------------------------------
// 2) RNN input GEMMs
// ---------------------------------------------------------------------------
__device__ __forceinline__ const float* feats_row(int rr) {
    int f = rr >> 14;
    int rem = rr & 16383;
    int bh4 = rem >> 9;
    int s   = rem & 511;
    int b = bh4 >> 2, hh = bh4 & 3;
    const float* src = (f == 0) ? g_q : (f == 1) ? g_k : g_v;
    return src + ((size_t)((b * H_ + 4 + hh) * S_ + s)) * DP_;
}

__global__ void __launch_bounds__(256) rnn_in_kernel(
    const float* __restrict__ bih_f, const float* __restrict__ bih_b) {
    const int z = blockIdx.z;
    const float* W    = z ? g_Wihbr : g_Wihfr;
    const float* bias = z ? bih_b : bih_f;
    float* dst        = z ? g_Bm : g_A;
    const int bm = blockIdx.y * 128;
    ca_tn(DP_,
        [&](int r, int k) { return feats_row(bm + r) + k; },
        [&](int r, int k) { return W + (size_t)r * DP_ + k; },
        [&](int il, int jl, float v) {
            dst[(size_t)(bm + il) * DP_ + jl] = v + bias[jl];
        });
}

// ---------------------------------------------------------------------------
// 3) First RNN step (elementwise; rounded out -- H1 feeds GEMMs)
// ---------------------------------------------------------------------------
__global__ void rnn_h1_kernel(const float* __restrict__ bih_f,
                              const float* __restrict__ bhh_f,
                              const float* __restrict__ bhh_b) {
    int gid = blockIdx.x * blockDim.x + threadIdx.x;
    if (gid >= NR_ * DP_) return;
    int r = gid >> 7, d = gid & 127;
    int s = r & 511;
    float af = s ? g_A[gid - DP_] : bih_f[d];
    g_H1f[gid] = rtf(tanhf(af + bhh_f[d]));
    g_H1b[gid] = rtf(tanhf(g_Bm[gid] + bhh_b[d]));
}

// ---------------------------------------------------------------------------
// 4) Forward step 2:  Yf = tanh( A + H1f@Whh_f^T + bhh_f )
// ---------------------------------------------------------------------------
__global__ void __launch_bounds__(256) rnn_h2f_kernel(const float* __restrict__ bhh_f) {
    const int bm = blockIdx.y * 128;
    ca_tn(DP_,
        [&](int r, int k) { return g_H1f + (size_t)(bm + r) * DP_ + k; },
        [&](int r, int k) { return g_Whhfr + (size_t)r * DP_ + k; },
        [&](int il, int jl, float v) {
            size_t idx = (size_t)(bm + il) * DP_ + jl;
            g_Yf[idx] = tanhf(v + g_A[idx] + bhh_f[jl]);
        });
}

// ---------------------------------------------------------------------------
// 5) Backward step 2 + combine + scatter back into q/k/v heads 4..7 (rounded)
// ---------------------------------------------------------------------------
__global__ void __launch_bounds__(256) rnn_h2b_kernel(
    const float* __restrict__ bih_b, const float* __restrict__ bhh_b) {
    const int bm = blockIdx.y * 128;
    ca_tn(DP_,
        [&](int r, int k) { return g_H1b + (size_t)(bm + r) * DP_ + k; },
        [&](int r, int k) { return g_Whhbr + (size_t)r * DP_ + k; },
        [&](int il, int jl, float v) {
            int m = bm + il, n = jl;
            int s = m & 511;
            float shiftB = s ? g_Bm[(size_t)(m - 1) * DP_ + n] : bih_b[n];
            float y = g_Yf[(size_t)m * DP_ + n] + tanhf(v + shiftB + bhh_b[n]);
            int f = m >> 14, rem = m & 16383, bh4 = rem >> 9;
            int b = bh4 >> 2, hh = bh4 & 3;
            float* dst = (f == 0) ? g_q : (f == 1) ? g_k : g_v;
            dst[((size_t)((b * H_ + 4 + hh) * S_ + s)) * DP_ + n] = rtf(y);
        });
}

// ---------------------------------------------------------------------------
// 6) P = (q . rel_emb^T)/SCALE as tf32 GEMM (M=32768, N=65 padded to 128)
// ---------------------------------------------------------------------------
__global__ void __launch_bounds__(256) p_gemm_kernel() {
    const int bm = blockIdx.y * 128;
    ca_tn(DP_,
        [&](int r, int k) { return g_q + (size_t)(bm + r) * DP_ + k; },
        [&](int r, int k) { return g_relr + (size_t)(r < 65 ? r : 64) * DP_ + k; },
        [&](int il, int jl, float v) {
            if (jl < 65) g_P[(size_t)(bm + il) * 65 + jl] = v * INV_SCALE;
        });
}

// ---------------------------------------------------------------------------
// 7) scores on COMPACTED keys -> g_attnc (pre-softmax)
// ---------------------------------------------------------------------------
__global__ void __launch_bounds__(256) scores_kernel() {
    const int z = blockIdx.z;
    const int b = z >> 3;
    const int L = g_nk[b];
    const int bm = blockIdx.y * 128, bn = blockIdx.x * 128;
    if (bn >= L) return;
    const float* qb = g_q + (size_t)z * S_ * DP_;
    const float* kb = g_kc + (size_t)z * S_ * DP_;
    const int* kid = g_kidx + b * S_;
    ca_tn(DP_,
        [&](int r, int k) { return qb + (size_t)(bm + r) * DP_ + k; },
        [&](int r, int k) { return kb + (size_t)(bn + r) * DP_ + k; },
        [&](int il, int jl, float v) {
            int qi = bm + il, jc = bn + jl;
            if (jc >= L) return;
            int ko = kid[jc];
            int off = ko - qi;
            off = off < -32 ? -32 : (off > 32 ? 32 : off);
            float val = v * INV_SCALE + g_P[((size_t)z * S_ + qi) * 65 + off + 32];
            g_attnc[((size_t)z * S_ + qi) * S_ + jc] = val;
        });
}

// ---------------------------------------------------------------------------
// 8) Softmax on compacted rows; dense attn output via inverse map; R buckets.
// ---------------------------------------------------------------------------
__device__ __forceinline__ float blk_reduce(float v, float* red, bool is_max) {
#pragma unroll
    for (int o = 16; o > 0; o >>= 1) {
        float w = __shfl_xor_sync(0xffffffffu, v, o);
        v = is_max ? fmaxf(v, w) : (v + w);
    }
    int warp = threadIdx.x >> 5, lane = threadIdx.x & 31;
    if (lane == 0) red[warp] = v;
    __syncthreads();
    float r = red[0];
#pragma unroll
    for (int i = 1; i < 8; i++) r = is_max ? fmaxf(r, red[i]) : (r + red[i]);
    __syncthreads();
    return r;
}

__global__ void __launch_bounds__(256) softmax_kernel(float* __restrict__ attn,
                                                      int attn_in_out) {
    float* ap = attn_in_out ? attn : g_attn_fb;
    int row = blockIdx.x;
    int z = row >> 9;
    int q = row & 511;
    int b = z >> 3;
    const int L = g_nk[b];
    const int Lpad = (L + 15) & ~15;
    float* pc = g_attnc + (size_t)row * S_;
    __shared__ float sh[S_];
    __shared__ float red[8];
    int t = threadIdx.x;
    float v0 = (t < L) ? pc[t] : -3.0e38f;
    float v1 = (t + 256 < L) ? pc[t + 256] : -3.0e38f;
    float mx = blk_reduce(fmaxf(v0, v1), red, true);
    float e0 = (t < L) ? expf(v0 - mx) : 0.f;
    float e1 = (t + 256 < L) ? expf(v1 - mx) : 0.f;
    float sum = blk_reduce(e0 + e1, red, false);
    float inv = 1.f / sum;
    e0 *= inv; e1 *= inv;
    // write back compacted (zero the K padding) + smem by position
    if (t < Lpad)       pc[t]       = e0;
    if (t + 256 < Lpad) pc[t + 256] = e1;
    sh[t] = e0; sh[t + 256] = e1;
    // zero middle R entries before scatter
    float* Rr = g_R + (size_t)row * RK_;
    if (t >= 1 && t <= 63) Rr[t] = 0.f;
    __syncthreads();
    // dense attn output via inverse map
    const int* kpos = g_kpos + b * S_;
    const int* msk  = g_mask + b * S_;
    float* apr = ap + (size_t)row * S_;
    apr[t]       = msk[t]       ? 0.f : sh[kpos[t]];
    apr[t + 256] = msk[t + 256] ? 0.f : sh[kpos[t + 256]];
    // R bucketing from compacted values
    const int* kid = g_kidx + b * S_;
    float r0 = 0.f, r64 = 0.f;
    if (t < L) {
        int ko = kid[t];
        if (ko <= q - 32)      r0  += e0;
        else if (ko >= q + 32) r64 += e0;
        else                   Rr[ko - q + 32] = e0;
    }
    if (t + 256 < L) {
        int ko = kid[t + 256];
        if (ko <= q - 32)      r0  += e1;
        else if (ko >= q + 32) r64 += e1;
        else                   Rr[ko - q + 32] = e1;
    }
    r0  = blk_reduce(r0,  red, false);
    r64 = blk_reduce(r64, red, false);
    if (t == 0) { Rr[0] = r0; Rr[64] = r64; }
}

// ---------------------------------------------------------------------------
// 9) ctx = attn_c @ vc  (NN, per bh, runtime K = ceil16(nk))
// ---------------------------------------------------------------------------
__global__ void __launch_bounds__(256) ctx_kernel() {
    const int z = blockIdx.z;
    const int b = z >> 3;
    int K = (g_nk[b] + 15) & ~15;
    if (K == 0) K = 16;   // degenerate; attn_c padding is zero
    const int bm = blockIdx.y * 128;
    const float* Ab = g_attnc + (size_t)z * S_ * S_;
    const float* Vb = g_vc + (size_t)z * S_ * DP_;
    ca_nn(K,
        [&](int r, int k) { return Ab + (size_t)(bm + r) * S_ + k; },
        [&](int k, int n) { return Vb + (size_t)k * DP_ + n; },
        [&](int il, int jl, float v) {
            g_ctx[(size_t)z * S_ * DP_ + (size_t)(bm + il) * DP_ + jl] = v;
        });
}

// ---------------------------------------------------------------------------
// 10) ctx += R @ rel_emb as tf32 GEMM (M=32768, N=128, K=80 padded)
// ---------------------------------------------------------------------------
__global__ void __launch_bounds__(256) ctx_rel_gemm_kernel() {
    const int bm = blockIdx.y * 128;
    ca_nn(RK_,
        [&](int r, int k) { return g_R + (size_t)(bm + r) * RK_ + k; },
        [&](int k, int n) { return g_relp + (size_t)k * DP_ + n; },
        [&](int il, int jl, float v) {
            size_t idx = (size_t)(bm + il) * DP_ + jl;
            g_ctx[idx] = rtf(g_ctx[idx] + v);
        });
}

// ---------------------------------------------------------------------------
// 11) out = ctx_perm @ Wo^T + bo
// ---------------------------------------------------------------------------
__global__ void __launch_bounds__(256) out_kernel(const float* __restrict__ bo,
                                                  float* __restrict__ out) {
    const int bm = blockIdx.y * 128, bn = blockIdx.x * 128;
    ca_tn(D_,
        [&](int r, int k) {
            int m = bm + r;
            int b = m >> 9, s = m & 511;
            int h = k >> 7, d = k & 127;
            return g_ctx + ((size_t)((b * H_ + h) * S_ + s)) * DP_ + d;
        },
        [&](int r, int k) { return g_Wor + (size_t)(bn + r) * D_ + k; },
        [&](int il, int jl, float v) {
            int m = bm + il, n = bn + jl;
            out[(size_t)m * D_ + n] = v + bo[n];
        });
}

// ---------------------------------------------------------------------------
// Host launcher
// ---------------------------------------------------------------------------
extern "C" void kernel_launch(void* const* d_in, const int* in_sizes, int n_in,
                              void* d_out, int out_size) {
    const float* x     = (const float*)d_in[0];
    const void*  mask  = d_in[1];
    const float* Wq    = (const float*)d_in[2];
    const float* bq    = (const float*)d_in[3];
    const float* Wk    = (const float*)d_in[4];
    const float* bk    = (const float*)d_in[5];
    const float* Wv    = (const float*)d_in[6];
    const float* bv    = (const float*)d_in[7];
    const float* Wo    = (const float*)d_in[8];
    const float* bo    = (const float*)d_in[9];
    const float* rel   = (const float*)d_in[10];
    const float* Wih_f = (const float*)d_in[11];
    const float* Whh_f = (const float*)d_in[12];
    const float* bih_f = (const float*)d_in[13];
    const float* bhh_f = (const float*)d_in[14];
    const float* Wih_b = (const float*)d_in[15];
    const float* Whh_b = (const float*)d_in[16];
    const float* bih_b = (const float*)d_in[17];
    const float* bhh_b = (const float*)d_in[18];

    float* out = (float*)d_out;
    const int attn_in_out = (out_size >= NOUT_ + BH_ * S_ * S_) ? 1 : 0;
    float* attn = attn_in_out ? (out + NOUT_) : nullptr;

    static int smem_set = 0;
    if (!smem_set) {
        cudaFuncSetAttribute(qkv_kernel,         cudaFuncAttributeMaxDynamicSharedMemorySize, SMEM_TN);
        cudaFuncSetAttribute(rnn_in_kernel,      cudaFuncAttributeMaxDynamicSharedMemorySize, SMEM_TN);
        cudaFuncSetAttribute(rnn_h2f_kernel,     cudaFuncAttributeMaxDynamicSharedMemorySize, SMEM_TN);
        cudaFuncSetAttribute(rnn_h2b_kernel,     cudaFuncAttributeMaxDynamicSharedMemorySize, SMEM_TN);
        cudaFuncSetAttribute(p_gemm_kernel,      cudaFuncAttributeMaxDynamicSharedMemorySize, SMEM_TN);
        cudaFuncSetAttribute(scores_kernel,      cudaFuncAttributeMaxDynamicSharedMemorySize, SMEM_TN);
        cudaFuncSetAttribute(ctx_kernel,         cudaFuncAttributeMaxDynamicSharedMemorySize, SMEM_NN);
        cudaFuncSetAttribute(ctx_rel_gemm_kernel,cudaFuncAttributeMaxDynamicSharedMemorySize, SMEM_NN);
        cudaFuncSetAttribute(out_kernel,         cudaFuncAttributeMaxDynamicSharedMemorySize, SMEM_TN);
        smem_set = 1;
    }

    // device pointers to rounded-copy buffers
    float* p_xr;  cudaGetSymbolAddress((void**)&p_xr,  g_xr);
    float* p_wq;  cudaGetSymbolAddress((void**)&p_wq,  g_Wqr);
    float* p_wk;  cudaGetSymbolAddress((void**)&p_wk,  g_Wkr);
    float* p_wv;  cudaGetSymbolAddress((void**)&p_wv,  g_Wvr);
    float* p_wo;  cudaGetSymbolAddress((void**)&p_wo,  g_Wor);
    float* p_wif; cudaGetSymbolAddress((void**)&p_wif, g_Wihfr);
    float* p_whf; cudaGetSymbolAddress((void**)&p_whf, g_Whhfr);
    float* p_wib; cudaGetSymbolAddress((void**)&p_wib, g_Wihbr);
    float* p_whb; cudaGetSymbolAddress((void**)&p_whb, g_Whhbr);

    // tf32 pre-rounding (rna): x, big weights (batched), rnn weights (batched), rel
    {
        int n4 = (MS_ * D_) / 4;
        round_kernel<<<(n4 + 255) / 256, 256>>>((const float4*)x, (float4*)p_xr, n4);
    }
    {
        int n4 = (D_ * D_) / 4;
        round4_kernel<<<dim3((n4 + 255) / 256, 4), 256>>>(
            (const float4*)Wq, (float4*)p_wq, (const float4*)Wk, (float4*)p_wk,
            (const float4*)Wv, (float4*)p_wv, (const float4*)Wo, (float4*)p_wo, n4);
    }
    {
        int n4 = (DP_ * DP_) / 4;
        round4_kernel<<<dim3((n4 + 255) / 256, 4), 256>>>(
            (const float4*)Wih_f, (float4*)p_wif, (const float4*)Whh_f, (float4*)p_whf,
            (const float4*)Wih_b, (float4*)p_wib, (const float4*)Whh_b, (float4*)p_whb, n4);
    }
    {
        int n4 = (65 * DP_) / 4;
        round_rel_kernel<<<(n4 + 255) / 256, 256>>>((const float4*)rel);
    }

    mask_norm_kernel<<<1, 1024>>>(mask);

    // zero-fill masked rows, then compute only unmasked rows
    zero_masked_kernel<<<(MS_ * D_ + 255) / 256, 256>>>();
    qkv_kernel<<<dim3(D_ / 128, MS_ / 128, 3), 256, SMEM_TN>>>(bq, bk, bv);

    rnn_in_kernel<<<dim3(1, NR_ / 128, 2), 256, SMEM_TN>>>(bih_f, bih_b);
    rnn_h1_kernel<<<(NR_ * DP_) / 256, 256>>>(bih_f, bhh_f, bhh_b);
    rnn_h2f_kernel<<<dim3(1, NR_ / 128), 256, SMEM_TN>>>(bhh_f);
    rnn_h2b_kernel<<<dim3(1, NR_ / 128), 256, SMEM_TN>>>(bih_b, bhh_b);

    // compacted keys/values (after RNN updates k/v)
    gather_kv_kernel<<<(BH_ * S_ * 32 + 255) / 256, 256>>>();

    p_gemm_kernel<<<dim3(1, ROWS_ / 128), 256, SMEM_TN>>>();

    scores_kernel<<<dim3(S_ / 128, S_ / 128, BH_), 256, SMEM_TN>>>();
    softmax_kernel<<<ROWS_, 256>>>(attn, attn_in_out);
    ctx_kernel<<<dim3(1, S_ / 128, BH_), 256, SMEM_NN>>>();
    ctx_rel_gemm_kernel<<<dim3(1, ROWS_ / 128), 256, SMEM_NN>>>();
    out_kernel<<<dim3(D_ / 128, MS_ / 128), 256, SMEM_TN>>>(bo, out);
}